// round 1
// baseline (speedup 1.0000x reference)
#include <cuda_runtime.h>
#include <math.h>

#define B 512
#define T 512
#define D 256
#define H 128        // IC_ENC == CI_ENC == 128
#define G 384        // 3*H
#define NDIR 4       // 0=ic_fwd, 1=ic_bwd, 2=ci_fwd, 3=ci_bwd
#define CLIPV 5.0f

// ---------------- device scratch (no runtime allocation allowed) ----------------
// x_all for all 4 directions, layout [m][1536] where m = b*T + t, col = dir*384 + g
__device__ float g_xall[(size_t)B * T * NDIR * G];   // 402,653,184 floats = 1.61 GB
// Whh repacked k-major, float4-friendly: float4 index = k4*G + g  (per dir)
__device__ float g_wpk[NDIR * G * H];                // 786 KB
// final hidden states of the ic encoder (fwd, bwd)
__device__ float g_hfinal[2 * B * H];

// ---------------- helpers ----------------
__device__ __forceinline__ float sigm(float x) {
    return 1.0f / (1.0f + __expf(-x));
}

// ---------------- kernel 0: repack Whh into k-major packed layout ----------------
__global__ void repack_whh(const float* __restrict__ icWhh,
                           const float* __restrict__ ciWhh) {
    int idx = blockIdx.x * blockDim.x + threadIdx.x;
    if (idx >= NDIR * G * H) return;
    int dir = idx / (G * H);
    int rem = idx % (G * H);
    int g = rem / H;
    int k = rem % H;
    const float* src = (dir < 2) ? (icWhh + (size_t)dir * G * H)
                                 : (ciWhh + (size_t)(dir - 2) * G * H);
    float v = src[(size_t)g * H + k];
    // packed: [dir][k>>2][g][k&3]
    g_wpk[(size_t)dir * G * H + (size_t)(k >> 2) * (G * 4) + g * 4 + (k & 3)] = v;
}

// ---------------- kernel 1: input projection GEMM ----------------
// C[m][n] = sum_k data[m][k] * W[n][k] + bih[n], m in [0,262144), n in [0,1536)
#define PBM 128
#define PBN 64
#define PBK 32
__global__ __launch_bounds__(256) void proj_gemm(
    const float* __restrict__ data,
    const float* __restrict__ icWih, const float* __restrict__ icBih,
    const float* __restrict__ ciWih, const float* __restrict__ ciBih) {

    __shared__ float As[PBK][PBM];       // k-major
    __shared__ float Bs[PBK][PBN + 4];   // k-major, padded

    int tid = threadIdx.x;
    int m0 = blockIdx.x * PBM;           // 2048 blocks
    int n0 = blockIdx.y * PBN;           // 24 blocks (PBN divides 384, so one dir per block)
    int tx = tid & 15;                   // n microtile (16 * 4 = 64)
    int ty = tid >> 4;                   // m microtile (16 * 8 = 128)

    int dir = n0 / G;
    int gbase = n0 - dir * G;
    const float* Wsel = (dir < 2) ? (icWih + (size_t)dir * G * D)
                                  : (ciWih + (size_t)(dir - 2) * G * D);
    const float* Bsel = (dir < 2) ? (icBih + dir * G) : (ciBih + (dir - 2) * G);

    float acc[8][4];
    #pragma unroll
    for (int i = 0; i < 8; i++)
        #pragma unroll
        for (int j = 0; j < 4; j++) acc[i][j] = 0.0f;

    for (int k0 = 0; k0 < D; k0 += PBK) {
        // load A tile: 128 rows x 32 k = 1024 float4, 4 per thread
        #pragma unroll
        for (int l = 0; l < 4; l++) {
            int f4 = tid + 256 * l;
            int row = f4 >> 3;
            int ks = f4 & 7;
            float4 v = *(const float4*)&data[(size_t)(m0 + row) * D + k0 + ks * 4];
            As[ks * 4 + 0][row] = v.x;
            As[ks * 4 + 1][row] = v.y;
            As[ks * 4 + 2][row] = v.z;
            As[ks * 4 + 3][row] = v.w;
        }
        // load B tile: 64 rows x 32 k = 512 float4, 2 per thread
        #pragma unroll
        for (int l = 0; l < 2; l++) {
            int f4 = tid + 256 * l;
            int row = f4 >> 3;
            int ks = f4 & 7;
            float4 v = *(const float4*)&Wsel[(size_t)(gbase + row) * D + k0 + ks * 4];
            Bs[ks * 4 + 0][row] = v.x;
            Bs[ks * 4 + 1][row] = v.y;
            Bs[ks * 4 + 2][row] = v.z;
            Bs[ks * 4 + 3][row] = v.w;
        }
        __syncthreads();

        #pragma unroll 8
        for (int k = 0; k < PBK; k++) {
            float a[8], bb[4];
            *(float4*)&a[0] = *(const float4*)&As[k][ty * 8];
            *(float4*)&a[4] = *(const float4*)&As[k][ty * 8 + 4];
            *(float4*)&bb[0] = *(const float4*)&Bs[k][tx * 4];
            #pragma unroll
            for (int i = 0; i < 8; i++)
                #pragma unroll
                for (int j = 0; j < 4; j++)
                    acc[i][j] += a[i] * bb[j];
        }
        __syncthreads();
    }

    // epilogue: add bias, store to g_xall
    int nb = n0 + tx * 4;
    float4 bv = *(const float4*)&Bsel[gbase + tx * 4];
    #pragma unroll
    for (int i = 0; i < 8; i++) {
        size_t m = (size_t)(m0 + ty * 8 + i);
        float4 o;
        o.x = acc[i][0] + bv.x;
        o.y = acc[i][1] + bv.y;
        o.z = acc[i][2] + bv.z;
        o.w = acc[i][3] + bv.w;
        *(float4*)&g_xall[m * (NDIR * G) + nb] = o;
    }
}

// ---------------- kernel 2: recurrent scan ----------------
// grid: 128 blocks = 4 dirs x 32 batch tiles of 16 rows; 256 threads
#define RT 16
__global__ __launch_bounds__(256) void scan_kernel(
    const float* __restrict__ icBhh, const float* __restrict__ ciBhh,
    const float* __restrict__ icH0, const float* __restrict__ ciH0,
    float* __restrict__ out) {

    __shared__ float hbuf[2][RT][H];   // ping-pong hidden state
    __shared__ float rh[RT][H];        // r * h
    __shared__ float zs[RT][H];        // z gate
    __shared__ float Cs[RT][256];      // h @ W_zr^T
    __shared__ float bsm[G];           // bhh

    int tid = threadIdx.x;
    int dir = blockIdx.x >> 5;
    int tile = blockIdx.x & 31;
    int b0 = tile * RT;

    const float* bhh = (dir < 2) ? (icBhh + dir * G) : (ciBhh + (dir - 2) * G);
    const float* h0 = (dir < 2) ? (icH0 + dir * H) : (ciH0 + (dir - 2) * H);
    const float4* wp4 = (const float4*)(g_wpk + (size_t)dir * G * H);

    for (int i = tid; i < G; i += 256) bsm[i] = bhh[i];
    for (int i = tid; i < RT * H; i += 256) hbuf[0][i / H][i % H] = h0[i % H];
    __syncthreads();

    int ping = 0;
    const bool backward = (dir & 1);
    const bool is_ci = (dir >= 2);
    // x_all row base for (b0, dir); row r at time t: + r*T*1536 + t*1536
    const float* xd = g_xall + (size_t)b0 * T * (NDIR * G) + dir * G;
    const size_t rowstride = (size_t)T * (NDIR * G);  // per batch row

    for (int step = 0; step < T; step++) {
        int t = backward ? (T - 1 - step) : step;
        const float* cur = &hbuf[ping][0][0];
        float* nxt = &hbuf[ping ^ 1][0][0];
        const float* xt = xd + (size_t)t * (NDIR * G);  // + r*rowstride per row

        // ---- GEMM1: Cs[r][j] = sum_k h[r][k] * W_zr[j][k], j in [0,256) ----
        {
            float c[RT];
            #pragma unroll
            for (int r = 0; r < RT; r++) c[r] = 0.0f;
            #pragma unroll 2
            for (int k4 = 0; k4 < H / 4; k4++) {
                float4 w = wp4[k4 * G + tid];
                #pragma unroll
                for (int r = 0; r < RT; r++) {
                    float4 hv = *(const float4*)&cur[r * H + k4 * 4];
                    c[r] += hv.x * w.x + hv.y * w.y + hv.z * w.z + hv.w * w.w;
                }
            }
            #pragma unroll
            for (int r = 0; r < RT; r++) Cs[r][tid] = c[r];
        }
        __syncthreads();

        // ---- gates z, r; build rh = r * h ----
        #pragma unroll
        for (int i = 0; i < 8; i++) {
            int idx = tid + 256 * i;      // 0..2047
            int r = idx >> 7;
            int g = idx & 127;
            const float* xrow = xt + (size_t)r * rowstride;
            float z = sigm(xrow[g] + bsm[g] + Cs[r][g]);
            float rr = sigm(xrow[g + 128] + bsm[g + 128] + Cs[r][g + 128]);
            zs[r][g] = z;
            rh[r][g] = rr * cur[r * H + g];
        }
        __syncthreads();

        // ---- GEMM2: c2[r] = sum_k rh[r][k] * W_n[g2][k]; update h ----
        {
            int g2 = tid & 127;
            int r0 = (tid >> 7) * 8;   // 0 or 8
            float c2[8];
            #pragma unroll
            for (int r = 0; r < 8; r++) c2[r] = 0.0f;
            #pragma unroll 2
            for (int k4 = 0; k4 < H / 4; k4++) {
                float4 w = wp4[k4 * G + 256 + g2];
                #pragma unroll
                for (int r = 0; r < 8; r++) {
                    float4 hv = *(const float4*)&rh[r0 + r][k4 * 4];
                    c2[r] += hv.x * w.x + hv.y * w.y + hv.z * w.z + hv.w * w.w;
                }
            }
            int slot = is_ci ? (dir == 2 ? t + 1 : t - 1) : 0;
            #pragma unroll
            for (int r = 0; r < 8; r++) {
                int rr = r0 + r;
                const float* xrow = xt + (size_t)rr * rowstride;
                float nv = tanhf(xrow[256 + g2] + bsm[256 + g2] + c2[r]);
                float z = zs[rr][g2];
                float hn = z * cur[rr * H + g2] + (1.0f - z) * nv;
                hn = fminf(CLIPV, fmaxf(-CLIPV, hn));
                nxt[rr * H + g2] = hn;
                if (is_ci && slot >= 0 && slot < T) {
                    size_t o = 65536 + (((size_t)(dir - 2) * B + (b0 + rr)) * T + slot) * H + g2;
                    out[o] = hn;
                }
            }
        }
        __syncthreads();
        ping ^= 1;
    }

    // ic encoders: save final hidden state
    if (dir < 2) {
        for (int i = tid; i < RT * H; i += 256) {
            int r = i / H, g = i % H;
            g_hfinal[((size_t)dir * B + b0 + r) * H + g] = hbuf[ping][r][g];
        }
    }
}

// ---------------- kernel 3: zero the lag-pad slots of ci ----------------
__global__ void zero_pads(float* __restrict__ out) {
    int b = blockIdx.x;
    int g = threadIdx.x;
    out[65536 + ((size_t)b * T + 0) * H + g] = 0.0f;                  // ci_fwd slot 0
    out[65536 + (((size_t)B + b) * T + (T - 1)) * H + g] = 0.0f;      // ci_bwd slot T-1
}

// ---------------- kernel 4: final linear -> ic_mean, ic_std ----------------
__global__ void final_linear(const float* __restrict__ Wl,
                             const float* __restrict__ bl,
                             float* __restrict__ out) {
    __shared__ float hsm[2 * H];
    int b = blockIdx.x;
    int j = threadIdx.x;  // 128 threads
    hsm[j] = g_hfinal[(size_t)b * H + j];            // fwd final
    hsm[H + j] = g_hfinal[((size_t)B + b) * H + j];  // bwd final
    __syncthreads();

    float acc = bl[j];
    const float4* w = (const float4*)&Wl[(size_t)j * (2 * H)];
    #pragma unroll 8
    for (int k4 = 0; k4 < (2 * H) / 4; k4++) {
        float4 wv = w[k4];
        float4 hv = *(const float4*)&hsm[k4 * 4];
        acc += wv.x * hv.x + wv.y * hv.y + wv.z * hv.z + wv.w * hv.w;
    }
    if (j < 64) out[(size_t)b * 64 + j] = acc;                      // ic_mean
    else out[32768 + (size_t)b * 64 + (j - 64)] = __expf(acc) * 0.0f + expf(acc);  // ic_std
}

// ---------------- launch ----------------
extern "C" void kernel_launch(void* const* d_in, const int* in_sizes, int n_in,
                              void* d_out, int out_size) {
    const float* data   = (const float*)d_in[0];
    const float* ic_h0  = (const float*)d_in[1];
    const float* ci_h0  = (const float*)d_in[2];
    const float* ic_Wih = (const float*)d_in[3];
    const float* ic_bih = (const float*)d_in[4];
    const float* ic_Whh = (const float*)d_in[5];
    const float* ic_bhh = (const float*)d_in[6];
    const float* ci_Wih = (const float*)d_in[7];
    const float* ci_bih = (const float*)d_in[8];
    const float* ci_Whh = (const float*)d_in[9];
    const float* ci_bhh = (const float*)d_in[10];
    const float* Wl     = (const float*)d_in[11];
    const float* bl     = (const float*)d_in[12];
    float* out = (float*)d_out;

    repack_whh<<<(NDIR * G * H + 255) / 256, 256>>>(ic_Whh, ci_Whh);

    dim3 pgrid(B * T / PBM, NDIR * G / PBN);  // 2048 x 24
    proj_gemm<<<pgrid, 256>>>(data, ic_Wih, ic_bih, ci_Wih, ci_bih);

    scan_kernel<<<NDIR * (B / RT), 256>>>(ic_bhh, ci_bhh, ic_h0, ci_h0, out);

    zero_pads<<<B, H>>>(out);
    final_linear<<<B, H>>>(Wl, bl, out);
}

// round 4
// speedup vs baseline: 1.1998x; 1.1998x over previous
#include <cuda_runtime.h>
#include <cuda_bf16.h>
#include <stdint.h>
#include <math.h>

#define B 512
#define T 512
#define D 256
#define H 128        // IC_ENC == CI_ENC == 128
#define G 384        // 3*H
#define NDIR 4       // 0=ic_fwd, 1=ic_bwd, 2=ci_fwd, 3=ci_bwd
#define CLIPV 5.0f
#define KP 768       // split-K'': [ah|al|ah] x [bh|bh|bl]
#define NTOT (NDIR * G)   // 1536

// ---------------- device scratch (no runtime allocation allowed) ----------------
__device__ float g_xall[(size_t)B * T * NTOT];              // 1.61 GB
__device__ float g_wpk[NDIR * G * H];                       // packed Whh
__device__ float g_hfinal[2 * B * H];
__device__ __nv_bfloat16 g_abf[(size_t)B * T * KP];         // A'' 402 MB
__device__ __nv_bfloat16 g_bbf[(size_t)NTOT * KP];          // B''
__device__ float g_bias[NTOT];

// ---------------- helpers ----------------
__device__ __forceinline__ float sigm(float x) {
    return 1.0f / (1.0f + __expf(-x));
}
__device__ __forceinline__ uint32_t smem_u32(const void* p) {
    uint32_t a;
    asm("{ .reg .u64 t; cvta.to.shared.u64 t, %1; cvt.u32.u64 %0, t; }" : "=r"(a) : "l"(p));
    return a;
}
__device__ __forceinline__ void cpasync16(uint32_t dst, const void* src) {
    asm volatile("cp.async.cg.shared.global [%0], [%1], 16;"
                 :: "r"(dst), "l"(__cvta_generic_to_global(src)) : "memory");
}
__device__ __forceinline__ void cpcommit() {
    asm volatile("cp.async.commit_group;" ::: "memory");
}
__device__ __forceinline__ void cpwait0() {
    asm volatile("cp.async.wait_group 0;" ::: "memory");
}
__device__ __forceinline__ void cpwait1() {
    asm volatile("cp.async.wait_group 1;" ::: "memory");
}
__device__ __forceinline__ void ldsm_x4(uint32_t* r, uint32_t addr) {
    asm volatile("ldmatrix.sync.aligned.m8n8.x4.shared.b16 {%0,%1,%2,%3}, [%4];"
                 : "=r"(r[0]), "=r"(r[1]), "=r"(r[2]), "=r"(r[3]) : "r"(addr));
}
__device__ __forceinline__ void ldsm_x2(uint32_t* r, uint32_t addr) {
    asm volatile("ldmatrix.sync.aligned.m8n8.x2.shared.b16 {%0,%1}, [%2];"
                 : "=r"(r[0]), "=r"(r[1]) : "r"(addr));
}
__device__ __forceinline__ void mma16816(float* d, const uint32_t* a, const uint32_t* b) {
    asm volatile(
        "mma.sync.aligned.m16n8k16.row.col.f32.bf16.bf16.f32 "
        "{%0,%1,%2,%3}, {%4,%5,%6,%7}, {%8,%9}, {%0,%1,%2,%3};"
        : "+f"(d[0]), "+f"(d[1]), "+f"(d[2]), "+f"(d[3])
        : "r"(a[0]), "r"(a[1]), "r"(a[2]), "r"(a[3]), "r"(b[0]), "r"(b[1]));
}

// ---------------- kernel 0: repack Whh into k-major packed layout ----------------
__global__ void repack_whh(const float* __restrict__ icWhh,
                           const float* __restrict__ ciWhh) {
    int idx = blockIdx.x * blockDim.x + threadIdx.x;
    if (idx >= NDIR * G * H) return;
    int dir = idx / (G * H);
    int rem = idx % (G * H);
    int g = rem / H;
    int k = rem % H;
    const float* src = (dir < 2) ? (icWhh + (size_t)dir * G * H)
                                 : (ciWhh + (size_t)(dir - 2) * G * H);
    float v = src[(size_t)g * H + k];
    g_wpk[(size_t)dir * G * H + (size_t)(k >> 2) * (G * 4) + g * 4 + (k & 3)] = v;
}

// ---------------- kernel 0b: split data into [ah|al|ah] bf16 rows of 768 ----------
__global__ __launch_bounds__(256) void conv_data(const float* __restrict__ data) {
    size_t i4 = (size_t)blockIdx.x * 256 + threadIdx.x;   // float4 index
    float4 v = ((const float4*)data)[i4];
    size_t m = i4 >> 6;          // 64 float4 per row of 256
    int k = (int)(i4 & 63) * 4;
    __nv_bfloat16 h0 = __float2bfloat16_rn(v.x);
    __nv_bfloat16 h1 = __float2bfloat16_rn(v.y);
    __nv_bfloat16 h2 = __float2bfloat16_rn(v.z);
    __nv_bfloat16 h3 = __float2bfloat16_rn(v.w);
    __nv_bfloat16 l0 = __float2bfloat16_rn(v.x - __bfloat162float(h0));
    __nv_bfloat16 l1 = __float2bfloat16_rn(v.y - __bfloat162float(h1));
    __nv_bfloat16 l2 = __float2bfloat16_rn(v.z - __bfloat162float(h2));
    __nv_bfloat16 l3 = __float2bfloat16_rn(v.w - __bfloat162float(h3));
    ushort4 hv, lv;
    hv.x = __bfloat16_as_ushort(h0); hv.y = __bfloat16_as_ushort(h1);
    hv.z = __bfloat16_as_ushort(h2); hv.w = __bfloat16_as_ushort(h3);
    lv.x = __bfloat16_as_ushort(l0); lv.y = __bfloat16_as_ushort(l1);
    lv.z = __bfloat16_as_ushort(l2); lv.w = __bfloat16_as_ushort(l3);
    __nv_bfloat16* row = g_abf + m * KP;
    *(ushort4*)&row[k] = hv;               // ah
    *(ushort4*)&row[256 + k] = lv;         // al
    *(ushort4*)&row[512 + k] = hv;         // ah (dup)
}

// ---------------- kernel 0c: split weights into [bh|bh|bl] + bias --------------
__global__ __launch_bounds__(256) void conv_w(
    const float* __restrict__ icWih, const float* __restrict__ icBih,
    const float* __restrict__ ciWih, const float* __restrict__ ciBih) {
    int idx = blockIdx.x * 256 + threadIdx.x;   // n*256 + k
    int n = idx >> 8;
    int k = idx & 255;
    int dir = n / G;
    int g = n - dir * G;
    const float* Wsel = (dir < 2) ? (icWih + (size_t)dir * G * D)
                                  : (ciWih + (size_t)(dir - 2) * G * D);
    const float* Bsel = (dir < 2) ? (icBih + dir * G) : (ciBih + (dir - 2) * G);
    float x = Wsel[(size_t)g * D + k];
    __nv_bfloat16 hi = __float2bfloat16_rn(x);
    __nv_bfloat16 lo = __float2bfloat16_rn(x - __bfloat162float(hi));
    __nv_bfloat16* row = g_bbf + (size_t)n * KP;
    row[k] = hi;             // bh
    row[256 + k] = hi;       // bh (dup)
    row[512 + k] = lo;       // bl
    if (k == 0) g_bias[n] = Bsel[g];
}

// ---------------- kernel 1: projection GEMM via mma.sync bf16 (HMMA) ------------
// C[m][n] = sum A''[m][k] B''[n][k] + bias[n]; M=262144, N=1536, K=768
// CTA tile 128x128x32, 8 warps (4m x 2n), warp tile 32x64, double-buffered cp.async
#define BK 32
#define NCH (KP / BK)      // 24
#define LDS_STRIDE 40      // bf16 elems per smem row (32 + 8 pad) -> 80 B
#define ABUF_B (128 * LDS_STRIDE * 2)   // 10240 B per buffer

__global__ __launch_bounds__(256) void proj_hmma() {
    __shared__ __nv_bfloat16 As[2][128][LDS_STRIDE];
    __shared__ __nv_bfloat16 Bs[2][128][LDS_STRIDE];
    __shared__ float bias_sm[128];

    int tid = threadIdx.x;
    int wid = tid >> 5;
    int lid = tid & 31;
    int wm = wid >> 1;            // 0..3
    int wn = wid & 1;             // 0..1

    int n0 = blockIdx.x * 128;            // 12 N-tiles (fastest -> A reuse in L2)
    size_t m0 = (size_t)blockIdx.y * 128; // 2048 M-tiles

    if (tid < 128) bias_sm[tid] = g_bias[n0 + tid];

    const __nv_bfloat16* Ag = g_abf + m0 * KP;
    const __nv_bfloat16* Bg = g_bbf + (size_t)n0 * KP;

    uint32_t sA = smem_u32(&As[0][0][0]);
    uint32_t sB = smem_u32(&Bs[0][0][0]);

    // per-thread load slots: 512 16B-chunks per tile, 2 per thread
    int r0 = tid >> 2, s0 = tid & 3;
    int r1 = (tid + 256) >> 2, s1 = (tid + 256) & 3;

    // ldmatrix address components
    int aRow = wm * 32 + (lid & 15);
    int aCol = (lid >> 4) * 16;           // bytes: 0 or 16
    int bRow = wn * 64 + (lid & 7);
    int bCol = ((lid >> 3) & 1) * 16;     // bytes

    float acc[2][8][4];
    #pragma unroll
    for (int mi = 0; mi < 2; mi++)
        #pragma unroll
        for (int nj = 0; nj < 8; nj++)
            #pragma unroll
            for (int q = 0; q < 4; q++) acc[mi][nj][q] = 0.0f;

    // prologue: load chunk 0 into buffer 0
    {
        cpasync16(sA + r0 * 80 + s0 * 16, Ag + (size_t)r0 * KP + s0 * 8);
        cpasync16(sA + r1 * 80 + s1 * 16, Ag + (size_t)r1 * KP + s1 * 8);
        cpasync16(sB + r0 * 80 + s0 * 16, Bg + (size_t)r0 * KP + s0 * 8);
        cpasync16(sB + r1 * 80 + s1 * 16, Bg + (size_t)r1 * KP + s1 * 8);
        cpcommit();
    }

    for (int i = 0; i < NCH; i++) {
        int buf = i & 1;
        if (i + 1 < NCH) {
            int nb = buf ^ 1;
            int kc = (i + 1) * BK;
            cpasync16(sA + nb * ABUF_B + r0 * 80 + s0 * 16, Ag + (size_t)r0 * KP + kc + s0 * 8);
            cpasync16(sA + nb * ABUF_B + r1 * 80 + s1 * 16, Ag + (size_t)r1 * KP + kc + s1 * 8);
            cpasync16(sB + nb * ABUF_B + r0 * 80 + s0 * 16, Bg + (size_t)r0 * KP + kc + s0 * 8);
            cpasync16(sB + nb * ABUF_B + r1 * 80 + s1 * 16, Bg + (size_t)r1 * KP + kc + s1 * 8);
            cpcommit();
            cpwait1();
        } else {
            cpwait0();
        }
        __syncthreads();

        uint32_t aBase = sA + buf * ABUF_B;
        uint32_t bBase = sB + buf * ABUF_B;
        #pragma unroll
        for (int ks = 0; ks < 2; ks++) {
            uint32_t afr[2][4];
            #pragma unroll
            for (int mi = 0; mi < 2; mi++)
                ldsm_x4(afr[mi], aBase + (aRow + mi * 16) * 80 + ks * 32 + aCol);
            uint32_t bfr[8][2];
            #pragma unroll
            for (int nj = 0; nj < 8; nj++)
                ldsm_x2(bfr[nj], bBase + (bRow + nj * 8) * 80 + ks * 32 + bCol);
            #pragma unroll
            for (int mi = 0; mi < 2; mi++)
                #pragma unroll
                for (int nj = 0; nj < 8; nj++)
                    mma16816(acc[mi][nj], afr[mi], bfr[nj]);
        }
        __syncthreads();
    }

    // epilogue: add bias, write fp32
    int qr = lid >> 2;
    int qc = (lid & 3) * 2;
    #pragma unroll
    for (int mi = 0; mi < 2; mi++) {
        #pragma unroll
        for (int nj = 0; nj < 8; nj++) {
            int lc = wn * 64 + nj * 8 + qc;
            size_t row = m0 + wm * 32 + mi * 16 + qr;
            float2 v0, v1;
            v0.x = acc[mi][nj][0] + bias_sm[lc];
            v0.y = acc[mi][nj][1] + bias_sm[lc + 1];
            v1.x = acc[mi][nj][2] + bias_sm[lc];
            v1.y = acc[mi][nj][3] + bias_sm[lc + 1];
            *(float2*)&g_xall[row * NTOT + n0 + lc] = v0;
            *(float2*)&g_xall[(row + 8) * NTOT + n0 + lc] = v1;
        }
    }
}

// ---------------- kernel 2: recurrent scan ----------------
#define RT 16
__global__ __launch_bounds__(256) void scan_kernel(
    const float* __restrict__ icBhh, const float* __restrict__ ciBhh,
    const float* __restrict__ icH0, const float* __restrict__ ciH0,
    float* __restrict__ out) {

    __shared__ float hbuf[2][RT][H];
    __shared__ float rh[RT][H];
    __shared__ float zs[RT][H];
    __shared__ float Cs[RT][256];
    __shared__ float bsm[G];

    int tid = threadIdx.x;
    int dir = blockIdx.x >> 5;
    int tile = blockIdx.x & 31;
    int b0 = tile * RT;

    const float* bhh = (dir < 2) ? (icBhh + dir * G) : (ciBhh + (dir - 2) * G);
    const float* h0 = (dir < 2) ? (icH0 + dir * H) : (ciH0 + (dir - 2) * H);
    const float4* wp4 = (const float4*)(g_wpk + (size_t)dir * G * H);

    for (int i = tid; i < G; i += 256) bsm[i] = bhh[i];
    for (int i = tid; i < RT * H; i += 256) hbuf[0][i / H][i % H] = h0[i % H];
    __syncthreads();

    int ping = 0;
    const bool backward = (dir & 1);
    const bool is_ci = (dir >= 2);
    const float* xd = g_xall + (size_t)b0 * T * NTOT + dir * G;
    const size_t rowstride = (size_t)T * NTOT;

    for (int step = 0; step < T; step++) {
        int t = backward ? (T - 1 - step) : step;
        const float* cur = &hbuf[ping][0][0];
        float* nxt = &hbuf[ping ^ 1][0][0];
        const float* xt = xd + (size_t)t * NTOT;

        // GEMM1: Cs[r][j] = sum_k h[r][k] * W_zr[j][k]
        {
            float c[RT];
            #pragma unroll
            for (int r = 0; r < RT; r++) c[r] = 0.0f;
            #pragma unroll 2
            for (int k4 = 0; k4 < H / 4; k4++) {
                float4 w = wp4[k4 * G + tid];
                #pragma unroll
                for (int r = 0; r < RT; r++) {
                    float4 hv = *(const float4*)&cur[r * H + k4 * 4];
                    c[r] += hv.x * w.x + hv.y * w.y + hv.z * w.z + hv.w * w.w;
                }
            }
            #pragma unroll
            for (int r = 0; r < RT; r++) Cs[r][tid] = c[r];
        }
        __syncthreads();

        // gates z, r; rh = r * h
        #pragma unroll
        for (int i = 0; i < 8; i++) {
            int idx = tid + 256 * i;
            int r = idx >> 7;
            int g = idx & 127;
            const float* xrow = xt + (size_t)r * rowstride;
            float z = sigm(xrow[g] + bsm[g] + Cs[r][g]);
            float rr = sigm(xrow[g + 128] + bsm[g + 128] + Cs[r][g + 128]);
            zs[r][g] = z;
            rh[r][g] = rr * cur[r * H + g];
        }
        __syncthreads();

        // GEMM2 + update
        {
            int g2 = tid & 127;
            int r0 = (tid >> 7) * 8;
            float c2[8];
            #pragma unroll
            for (int r = 0; r < 8; r++) c2[r] = 0.0f;
            #pragma unroll 2
            for (int k4 = 0; k4 < H / 4; k4++) {
                float4 w = wp4[k4 * G + 256 + g2];
                #pragma unroll
                for (int r = 0; r < 8; r++) {
                    float4 hv = *(const float4*)&rh[r0 + r][k4 * 4];
                    c2[r] += hv.x * w.x + hv.y * w.y + hv.z * w.z + hv.w * w.w;
                }
            }
            int slot = is_ci ? (dir == 2 ? t + 1 : t - 1) : 0;
            #pragma unroll
            for (int r = 0; r < 8; r++) {
                int rr = r0 + r;
                const float* xrow = xt + (size_t)rr * rowstride;
                float nv = tanhf(xrow[256 + g2] + bsm[256 + g2] + c2[r]);
                float z = zs[rr][g2];
                float hn = z * cur[rr * H + g2] + (1.0f - z) * nv;
                hn = fminf(CLIPV, fmaxf(-CLIPV, hn));
                nxt[rr * H + g2] = hn;
                if (is_ci && slot >= 0 && slot < T) {
                    size_t o = 65536 + (((size_t)(dir - 2) * B + (b0 + rr)) * T + slot) * H + g2;
                    out[o] = hn;
                }
            }
        }
        __syncthreads();
        ping ^= 1;
    }

    if (dir < 2) {
        for (int i = tid; i < RT * H; i += 256) {
            int r = i / H, g = i % H;
            g_hfinal[((size_t)dir * B + b0 + r) * H + g] = hbuf[ping][r][g];
        }
    }
}

// ---------------- kernel 3: zero the lag-pad slots of ci ----------------
__global__ void zero_pads(float* __restrict__ out) {
    int b = blockIdx.x;
    int g = threadIdx.x;
    out[65536 + ((size_t)b * T + 0) * H + g] = 0.0f;
    out[65536 + (((size_t)B + b) * T + (T - 1)) * H + g] = 0.0f;
}

// ---------------- kernel 4: final linear -> ic_mean, ic_std ----------------
__global__ void final_linear(const float* __restrict__ Wl,
                             const float* __restrict__ bl,
                             float* __restrict__ out) {
    __shared__ float hsm[2 * H];
    int b = blockIdx.x;
    int j = threadIdx.x;
    hsm[j] = g_hfinal[(size_t)b * H + j];
    hsm[H + j] = g_hfinal[((size_t)B + b) * H + j];
    __syncthreads();

    float acc = bl[j];
    const float4* w = (const float4*)&Wl[(size_t)j * (2 * H)];
    #pragma unroll 8
    for (int k4 = 0; k4 < (2 * H) / 4; k4++) {
        float4 wv = w[k4];
        float4 hv = *(const float4*)&hsm[k4 * 4];
        acc += wv.x * hv.x + wv.y * hv.y + wv.z * hv.z + wv.w * hv.w;
    }
    if (j < 64) out[(size_t)b * 64 + j] = acc;
    else out[32768 + (size_t)b * 64 + (j - 64)] = expf(acc);
}

// ---------------- launch ----------------
extern "C" void kernel_launch(void* const* d_in, const int* in_sizes, int n_in,
                              void* d_out, int out_size) {
    const float* data   = (const float*)d_in[0];
    const float* ic_h0  = (const float*)d_in[1];
    const float* ci_h0  = (const float*)d_in[2];
    const float* ic_Wih = (const float*)d_in[3];
    const float* ic_bih = (const float*)d_in[4];
    const float* ic_Whh = (const float*)d_in[5];
    const float* ic_bhh = (const float*)d_in[6];
    const float* ci_Wih = (const float*)d_in[7];
    const float* ci_bih = (const float*)d_in[8];
    const float* ci_Whh = (const float*)d_in[9];
    const float* ci_bhh = (const float*)d_in[10];
    const float* Wl     = (const float*)d_in[11];
    const float* bl     = (const float*)d_in[12];
    float* out = (float*)d_out;

    repack_whh<<<(NDIR * G * H + 255) / 256, 256>>>(ic_Whh, ci_Whh);
    conv_data<<<(int)((size_t)B * T * D / 4 / 256), 256>>>(data);
    conv_w<<<NTOT, 256>>>(ic_Wih, ic_bih, ci_Wih, ci_bih);

    dim3 pgrid(NTOT / 128, B * T / 128);   // 12 x 2048
    proj_hmma<<<pgrid, 256>>>();

    scan_kernel<<<NDIR * (B / RT), 256>>>(ic_bhh, ci_bhh, ic_h0, ci_h0, out);

    zero_pads<<<B, H>>>(out);
    final_linear<<<B, H>>>(Wl, bl, out);
}

// round 5
// speedup vs baseline: 2.5157x; 2.0967x over previous
#include <cuda_runtime.h>
#include <cuda_bf16.h>
#include <stdint.h>
#include <math.h>

#define B 512
#define T 512
#define D 256
#define H 128        // IC_ENC == CI_ENC == 128
#define G 384        // 3*H
#define NDIR 4       // 0=ic_fwd, 1=ic_bwd, 2=ci_fwd, 3=ci_bwd
#define CLIPV 5.0f
#define KP 768       // split-K'': [ah|al|ah] x [bh|bh|bl]
#define NTOT (NDIR * G)   // 1536

// ---------------- device scratch (no runtime allocation allowed) ----------------
__device__ float g_xall[(size_t)B * T * NTOT];              // 1.61 GB
__device__ float g_wpk[NDIR * G * H];                       // packed Whh
__device__ float g_hfinal[2 * B * H];
__device__ __nv_bfloat16 g_abf[(size_t)B * T * KP];         // A'' 402 MB
__device__ __nv_bfloat16 g_bbf[(size_t)NTOT * KP];          // B''
__device__ float g_bias[NTOT];                              // bih + bhh (folded)

// ---------------- helpers ----------------
__device__ __forceinline__ float sigm(float x) {
    return 1.0f / (1.0f + __expf(-x));
}
__device__ __forceinline__ uint32_t smem_u32(const void* p) {
    uint32_t a;
    asm("{ .reg .u64 t; cvta.to.shared.u64 t, %1; cvt.u32.u64 %0, t; }" : "=r"(a) : "l"(p));
    return a;
}
__device__ __forceinline__ void cpasync16(uint32_t dst, const void* src) {
    asm volatile("cp.async.cg.shared.global [%0], [%1], 16;"
                 :: "r"(dst), "l"(__cvta_generic_to_global(src)) : "memory");
}
__device__ __forceinline__ void cpcommit() {
    asm volatile("cp.async.commit_group;" ::: "memory");
}
__device__ __forceinline__ void cpwait0() {
    asm volatile("cp.async.wait_group 0;" ::: "memory");
}
__device__ __forceinline__ void cpwait1() {
    asm volatile("cp.async.wait_group 1;" ::: "memory");
}
__device__ __forceinline__ void ldsm_x4(uint32_t* r, uint32_t addr) {
    asm volatile("ldmatrix.sync.aligned.m8n8.x4.shared.b16 {%0,%1,%2,%3}, [%4];"
                 : "=r"(r[0]), "=r"(r[1]), "=r"(r[2]), "=r"(r[3]) : "r"(addr));
}
__device__ __forceinline__ void ldsm_x2(uint32_t* r, uint32_t addr) {
    asm volatile("ldmatrix.sync.aligned.m8n8.x2.shared.b16 {%0,%1}, [%2];"
                 : "=r"(r[0]), "=r"(r[1]) : "r"(addr));
}
__device__ __forceinline__ void mma16816(float* d, const uint32_t* a, const uint32_t* b) {
    asm volatile(
        "mma.sync.aligned.m16n8k16.row.col.f32.bf16.bf16.f32 "
        "{%0,%1,%2,%3}, {%4,%5,%6,%7}, {%8,%9}, {%0,%1,%2,%3};"
        : "+f"(d[0]), "+f"(d[1]), "+f"(d[2]), "+f"(d[3])
        : "r"(a[0]), "r"(a[1]), "r"(a[2]), "r"(a[3]), "r"(b[0]), "r"(b[1]));
}
// packed fp32x2 FMA: d = a*b + d elementwise on two lanes
__device__ __forceinline__ void ffma2(unsigned long long& d, unsigned long long a,
                                      unsigned long long b) {
    asm("fma.rn.f32x2 %0, %1, %2, %0;" : "+l"(d) : "l"(a), "l"(b));
}
__device__ __forceinline__ float hsum2(unsigned long long v) {
    float2 f = *(float2*)&v;
    return f.x + f.y;
}

// ---------------- kernel 0: repack Whh into k-major packed layout ----------------
__global__ void repack_whh(const float* __restrict__ icWhh,
                           const float* __restrict__ ciWhh) {
    int idx = blockIdx.x * blockDim.x + threadIdx.x;
    if (idx >= NDIR * G * H) return;
    int dir = idx / (G * H);
    int rem = idx % (G * H);
    int g = rem / H;
    int k = rem % H;
    const float* src = (dir < 2) ? (icWhh + (size_t)dir * G * H)
                                 : (ciWhh + (size_t)(dir - 2) * G * H);
    float v = src[(size_t)g * H + k];
    g_wpk[(size_t)dir * G * H + (size_t)(k >> 2) * (G * 4) + g * 4 + (k & 3)] = v;
}

// ---------------- kernel 0b: split data into [ah|al|ah] bf16 rows of 768 ----------
__global__ __launch_bounds__(256) void conv_data(const float* __restrict__ data) {
    size_t i4 = (size_t)blockIdx.x * 256 + threadIdx.x;   // float4 index
    float4 v = ((const float4*)data)[i4];
    size_t m = i4 >> 6;          // 64 float4 per row of 256
    int k = (int)(i4 & 63) * 4;
    __nv_bfloat16 h0 = __float2bfloat16_rn(v.x);
    __nv_bfloat16 h1 = __float2bfloat16_rn(v.y);
    __nv_bfloat16 h2 = __float2bfloat16_rn(v.z);
    __nv_bfloat16 h3 = __float2bfloat16_rn(v.w);
    __nv_bfloat16 l0 = __float2bfloat16_rn(v.x - __bfloat162float(h0));
    __nv_bfloat16 l1 = __float2bfloat16_rn(v.y - __bfloat162float(h1));
    __nv_bfloat16 l2 = __float2bfloat16_rn(v.z - __bfloat162float(h2));
    __nv_bfloat16 l3 = __float2bfloat16_rn(v.w - __bfloat162float(h3));
    ushort4 hv, lv;
    hv.x = __bfloat16_as_ushort(h0); hv.y = __bfloat16_as_ushort(h1);
    hv.z = __bfloat16_as_ushort(h2); hv.w = __bfloat16_as_ushort(h3);
    lv.x = __bfloat16_as_ushort(l0); lv.y = __bfloat16_as_ushort(l1);
    lv.z = __bfloat16_as_ushort(l2); lv.w = __bfloat16_as_ushort(l3);
    __nv_bfloat16* row = g_abf + m * KP;
    *(ushort4*)&row[k] = hv;               // ah
    *(ushort4*)&row[256 + k] = lv;         // al
    *(ushort4*)&row[512 + k] = hv;         // ah (dup)
}

// ---------------- kernel 0c: split weights into [bh|bh|bl] + folded bias ----------
__global__ __launch_bounds__(256) void conv_w(
    const float* __restrict__ icWih, const float* __restrict__ icBih,
    const float* __restrict__ ciWih, const float* __restrict__ ciBih,
    const float* __restrict__ icBhh, const float* __restrict__ ciBhh) {
    int idx = blockIdx.x * 256 + threadIdx.x;   // n*256 + k
    int n = idx >> 8;
    int k = idx & 255;
    int dir = n / G;
    int g = n - dir * G;
    const float* Wsel = (dir < 2) ? (icWih + (size_t)dir * G * D)
                                  : (ciWih + (size_t)(dir - 2) * G * D);
    const float* Bsel = (dir < 2) ? (icBih + dir * G) : (ciBih + (dir - 2) * G);
    const float* Bhh  = (dir < 2) ? (icBhh + dir * G) : (ciBhh + (dir - 2) * G);
    float x = Wsel[(size_t)g * D + k];
    __nv_bfloat16 hi = __float2bfloat16_rn(x);
    __nv_bfloat16 lo = __float2bfloat16_rn(x - __bfloat162float(hi));
    __nv_bfloat16* row = g_bbf + (size_t)n * KP;
    row[k] = hi;             // bh
    row[256 + k] = hi;       // bh (dup)
    row[512 + k] = lo;       // bl
    if (k == 0) g_bias[n] = Bsel[g] + Bhh[g];   // fold recurrent bias
}

// ---------------- kernel 1: projection GEMM via mma.sync bf16 (HMMA) ------------
#define BK 32
#define NCH (KP / BK)      // 24
#define LDS_STRIDE 40      // bf16 elems per smem row (32 + 8 pad) -> 80 B
#define ABUF_B (128 * LDS_STRIDE * 2)   // 10240 B per buffer

__global__ __launch_bounds__(256) void proj_hmma() {
    __shared__ __nv_bfloat16 As[2][128][LDS_STRIDE];
    __shared__ __nv_bfloat16 Bs[2][128][LDS_STRIDE];
    __shared__ float bias_sm[128];

    int tid = threadIdx.x;
    int wid = tid >> 5;
    int lid = tid & 31;
    int wm = wid >> 1;            // 0..3
    int wn = wid & 1;             // 0..1

    int n0 = blockIdx.x * 128;            // 12 N-tiles (fastest -> A reuse in L2)
    size_t m0 = (size_t)blockIdx.y * 128; // 2048 M-tiles

    if (tid < 128) bias_sm[tid] = g_bias[n0 + tid];

    const __nv_bfloat16* Ag = g_abf + m0 * KP;
    const __nv_bfloat16* Bg = g_bbf + (size_t)n0 * KP;

    uint32_t sA = smem_u32(&As[0][0][0]);
    uint32_t sB = smem_u32(&Bs[0][0][0]);

    int r0 = tid >> 2, s0 = tid & 3;
    int r1 = (tid + 256) >> 2, s1 = (tid + 256) & 3;

    int aRow = wm * 32 + (lid & 15);
    int aCol = (lid >> 4) * 16;
    int bRow = wn * 64 + (lid & 7);
    int bCol = ((lid >> 3) & 1) * 16;

    float acc[2][8][4];
    #pragma unroll
    for (int mi = 0; mi < 2; mi++)
        #pragma unroll
        for (int nj = 0; nj < 8; nj++)
            #pragma unroll
            for (int q = 0; q < 4; q++) acc[mi][nj][q] = 0.0f;

    {
        cpasync16(sA + r0 * 80 + s0 * 16, Ag + (size_t)r0 * KP + s0 * 8);
        cpasync16(sA + r1 * 80 + s1 * 16, Ag + (size_t)r1 * KP + s1 * 8);
        cpasync16(sB + r0 * 80 + s0 * 16, Bg + (size_t)r0 * KP + s0 * 8);
        cpasync16(sB + r1 * 80 + s1 * 16, Bg + (size_t)r1 * KP + s1 * 8);
        cpcommit();
    }

    for (int i = 0; i < NCH; i++) {
        int buf = i & 1;
        if (i + 1 < NCH) {
            int nb = buf ^ 1;
            int kc = (i + 1) * BK;
            cpasync16(sA + nb * ABUF_B + r0 * 80 + s0 * 16, Ag + (size_t)r0 * KP + kc + s0 * 8);
            cpasync16(sA + nb * ABUF_B + r1 * 80 + s1 * 16, Ag + (size_t)r1 * KP + kc + s1 * 8);
            cpasync16(sB + nb * ABUF_B + r0 * 80 + s0 * 16, Bg + (size_t)r0 * KP + kc + s0 * 8);
            cpasync16(sB + nb * ABUF_B + r1 * 80 + s1 * 16, Bg + (size_t)r1 * KP + kc + s1 * 8);
            cpcommit();
            cpwait1();
        } else {
            cpwait0();
        }
        __syncthreads();

        uint32_t aBase = sA + buf * ABUF_B;
        uint32_t bBase = sB + buf * ABUF_B;
        #pragma unroll
        for (int ks = 0; ks < 2; ks++) {
            uint32_t afr[2][4];
            #pragma unroll
            for (int mi = 0; mi < 2; mi++)
                ldsm_x4(afr[mi], aBase + (aRow + mi * 16) * 80 + ks * 32 + aCol);
            uint32_t bfr[8][2];
            #pragma unroll
            for (int nj = 0; nj < 8; nj++)
                ldsm_x2(bfr[nj], bBase + (bRow + nj * 8) * 80 + ks * 32 + bCol);
            #pragma unroll
            for (int mi = 0; mi < 2; mi++)
                #pragma unroll
                for (int nj = 0; nj < 8; nj++)
                    mma16816(acc[mi][nj], afr[mi], bfr[nj]);
        }
        __syncthreads();
    }

    int qr = lid >> 2;
    int qc = (lid & 3) * 2;
    #pragma unroll
    for (int mi = 0; mi < 2; mi++) {
        #pragma unroll
        for (int nj = 0; nj < 8; nj++) {
            int lc = wn * 64 + nj * 8 + qc;
            size_t row = m0 + wm * 32 + mi * 16 + qr;
            float2 v0, v1;
            v0.x = acc[mi][nj][0] + bias_sm[lc];
            v0.y = acc[mi][nj][1] + bias_sm[lc + 1];
            v1.x = acc[mi][nj][2] + bias_sm[lc];
            v1.y = acc[mi][nj][3] + bias_sm[lc + 1];
            *(float2*)&g_xall[row * NTOT + n0 + lc] = v0;
            *(float2*)&g_xall[(row + 8) * NTOT + n0 + lc] = v1;
        }
    }
}

// ---------------- kernel 2: recurrent scan (SMEM-resident W, FFMA2) --------------
#define RT 16
// dynamic smem layout (floats): Wsm[49152] | h[2048] | rh[2048] | Cs[4096]
#define SMEM_SCAN ((49152 + 2048 + 2048 + 4096) * 4)   // 229376 B

__global__ __launch_bounds__(256) void scan_kernel(
    const float* __restrict__ icH0, const float* __restrict__ ciH0,
    float* __restrict__ out) {

    extern __shared__ float sm[];
    float* Wsm = sm;                 // packed [k4][g][4], g in [0,384)
    float* hb  = sm + 49152;         // RT*H
    float* rh  = sm + 49152 + 2048;  // RT*H
    float* Cs  = sm + 49152 + 4096;  // RT rows x 256 cols

    int tid = threadIdx.x;
    int dir = blockIdx.x >> 5;
    int tile = blockIdx.x & 31;
    int b0 = tile * RT;

    const float* h0 = (dir < 2) ? (icH0 + dir * H) : (ciH0 + (dir - 2) * H);

    // load W into SMEM (192 KB), h0 into h
    {
        const float4* wg = (const float4*)(g_wpk + (size_t)dir * G * H);
        float4* Wsm4 = (float4*)Wsm;
        #pragma unroll
        for (int i = 0; i < (G * H / 4) / 256; i++)
            Wsm4[tid + 256 * i] = wg[tid + 256 * i];
        for (int i = tid; i < RT * H; i += 256) hb[i] = h0[i % H];
    }
    __syncthreads();

    const bool backward = (dir & 1);
    const bool is_ci = (dir >= 2);
    const float* xbase = g_xall + (size_t)b0 * T * NTOT + dir * G;
    const size_t rowstride = (size_t)T * NTOT;

    int g2 = tid & 127;
    int r0 = (tid >> 7) * 8;   // 0 or 8

    for (int step = 0; step < T; step++) {
        int t = backward ? (T - 1 - step) : step;
        const float* xt = xbase + (size_t)t * NTOT;

        // prefetch this step's x values into registers (hidden under GEMM1)
        float xz[8], xr[8], xn[8];
        #pragma unroll
        for (int i = 0; i < 8; i++) {
            const float* xrow = xt + (size_t)(r0 + i) * rowstride;
            xz[i] = __ldg(&xrow[g2]);
            xr[i] = __ldg(&xrow[g2 + 128]);
            xn[i] = __ldg(&xrow[g2 + 256]);
        }

        // ---- GEMM1: Cs[r][tid] = sum_k h[r][k] * W_zr[tid][k]  (FFMA2) ----
        {
            unsigned long long acc[RT];
            #pragma unroll
            for (int r = 0; r < RT; r++) acc[r] = 0ull;
            #pragma unroll 4
            for (int k4 = 0; k4 < H / 4; k4++) {
                ulonglong2 w = *(const ulonglong2*)(Wsm + (size_t)(k4 * G + tid) * 4);
                #pragma unroll
                for (int r = 0; r < RT; r++) {
                    ulonglong2 hv = *(const ulonglong2*)(hb + r * H + k4 * 4);
                    ffma2(acc[r], hv.x, w.x);
                    ffma2(acc[r], hv.y, w.y);
                }
            }
            #pragma unroll
            for (int r = 0; r < RT; r++) Cs[r * 256 + tid] = hsum2(acc[r]);
        }
        __syncthreads();

        // ---- gates: z stays in registers; rh = r * h ----
        float z[8];
        #pragma unroll
        for (int i = 0; i < 8; i++) {
            int r = r0 + i;
            float zz = sigm(xz[i] + Cs[r * 256 + g2]);
            float rr = sigm(xr[i] + Cs[r * 256 + g2 + 128]);
            z[i] = zz;
            rh[r * H + g2] = rr * hb[r * H + g2];
        }
        __syncthreads();

        // ---- GEMM2: c2[i] = sum_k rh[r0+i][k] * W_n[g2][k]; update h ----
        {
            unsigned long long acc[8];
            #pragma unroll
            for (int i = 0; i < 8; i++) acc[i] = 0ull;
            #pragma unroll 4
            for (int k4 = 0; k4 < H / 4; k4++) {
                ulonglong2 w = *(const ulonglong2*)(Wsm + (size_t)(k4 * G + 256 + g2) * 4);
                #pragma unroll
                for (int i = 0; i < 8; i++) {
                    ulonglong2 hv = *(const ulonglong2*)(rh + (r0 + i) * H + k4 * 4);
                    ffma2(acc[i], hv.x, w.x);
                    ffma2(acc[i], hv.y, w.y);
                }
            }
            int slot = is_ci ? (dir == 2 ? t + 1 : t - 1) : 0;
            #pragma unroll
            for (int i = 0; i < 8; i++) {
                int rr = r0 + i;
                float nv = tanhf(xn[i] + hsum2(acc[i]));
                float hn = z[i] * hb[rr * H + g2] + (1.0f - z[i]) * nv;
                hn = fminf(CLIPV, fmaxf(-CLIPV, hn));
                hb[rr * H + g2] = hn;
                if (is_ci && slot >= 0 && slot < T) {
                    size_t o = 65536 + (((size_t)(dir - 2) * B + (b0 + rr)) * T + slot) * H + g2;
                    out[o] = hn;
                }
            }
        }
        __syncthreads();
    }

    if (dir < 2) {
        for (int i = tid; i < RT * H; i += 256) {
            int r = i / H, g = i % H;
            g_hfinal[((size_t)dir * B + b0 + r) * H + g] = hb[r * H + g];
        }
    }
}

// ---------------- kernel 3: zero the lag-pad slots of ci ----------------
__global__ void zero_pads(float* __restrict__ out) {
    int b = blockIdx.x;
    int g = threadIdx.x;
    out[65536 + ((size_t)b * T + 0) * H + g] = 0.0f;
    out[65536 + (((size_t)B + b) * T + (T - 1)) * H + g] = 0.0f;
}

// ---------------- kernel 4: final linear -> ic_mean, ic_std ----------------
__global__ void final_linear(const float* __restrict__ Wl,
                             const float* __restrict__ bl,
                             float* __restrict__ out) {
    __shared__ float hsm[2 * H];
    int b = blockIdx.x;
    int j = threadIdx.x;
    hsm[j] = g_hfinal[(size_t)b * H + j];
    hsm[H + j] = g_hfinal[((size_t)B + b) * H + j];
    __syncthreads();

    float acc = bl[j];
    const float4* w = (const float4*)&Wl[(size_t)j * (2 * H)];
    #pragma unroll 8
    for (int k4 = 0; k4 < (2 * H) / 4; k4++) {
        float4 wv = w[k4];
        float4 hv = *(const float4*)&hsm[k4 * 4];
        acc += wv.x * hv.x + wv.y * hv.y + wv.z * hv.z + wv.w * hv.w;
    }
    if (j < 64) out[(size_t)b * 64 + j] = acc;
    else out[32768 + (size_t)b * 64 + (j - 64)] = expf(acc);
}

// ---------------- launch ----------------
extern "C" void kernel_launch(void* const* d_in, const int* in_sizes, int n_in,
                              void* d_out, int out_size) {
    const float* data   = (const float*)d_in[0];
    const float* ic_h0  = (const float*)d_in[1];
    const float* ci_h0  = (const float*)d_in[2];
    const float* ic_Wih = (const float*)d_in[3];
    const float* ic_bih = (const float*)d_in[4];
    const float* ic_Whh = (const float*)d_in[5];
    const float* ic_bhh = (const float*)d_in[6];
    const float* ci_Wih = (const float*)d_in[7];
    const float* ci_bih = (const float*)d_in[8];
    const float* ci_Whh = (const float*)d_in[9];
    const float* ci_bhh = (const float*)d_in[10];
    const float* Wl     = (const float*)d_in[11];
    const float* bl     = (const float*)d_in[12];
    float* out = (float*)d_out;

    cudaFuncSetAttribute(scan_kernel, cudaFuncAttributeMaxDynamicSharedMemorySize, SMEM_SCAN);

    repack_whh<<<(NDIR * G * H + 255) / 256, 256>>>(ic_Whh, ci_Whh);
    conv_data<<<(int)((size_t)B * T * D / 4 / 256), 256>>>(data);
    conv_w<<<NTOT, 256>>>(ic_Wih, ic_bih, ci_Wih, ci_bih, ic_bhh, ci_bhh);

    dim3 pgrid(NTOT / 128, B * T / 128);   // 12 x 2048
    proj_hmma<<<pgrid, 256>>>();

    scan_kernel<<<NDIR * (B / RT), 256, SMEM_SCAN>>>(ic_h0, ci_h0, out);

    zero_pads<<<B, H>>>(out);
    final_linear<<<B, H>>>(Wl, bl, out);
}

// round 6
// speedup vs baseline: 2.5825x; 1.0266x over previous
#include <cuda_runtime.h>
#include <cuda_bf16.h>
#include <stdint.h>
#include <math.h>

#define B 512
#define T 512
#define D 256
#define H 128        // IC_ENC == CI_ENC == 128
#define G 384        // 3*H
#define NDIR 4       // 0=ic_fwd, 1=ic_bwd, 2=ci_fwd, 3=ci_bwd
#define CLIPV 5.0f
#define KP 768       // logical split-K'': [ah|al|ah] x [bh|bh|bl]
#define KPA 512      // stored A width: [ah|al] (third block re-reads ah)
#define NTOT (NDIR * G)   // 1536

// ---------------- device scratch (no runtime allocation allowed) ----------------
__device__ float g_xall[(size_t)B * T * NTOT];              // 1.61 GB
__device__ float g_wpk[NDIR * G * H];                       // packed Whh
__device__ float g_hfinal[2 * B * H];
__device__ __nv_bfloat16 g_abf[(size_t)B * T * KPA];        // A'' 268 MB
__device__ __nv_bfloat16 g_bbf[(size_t)NTOT * KP];          // B''
__device__ float g_bias[NTOT];                              // bih + bhh (folded)

// ---------------- helpers ----------------
__device__ __forceinline__ float sigm(float x) {
    return 1.0f / (1.0f + __expf(-x));
}
__device__ __forceinline__ uint32_t smem_u32(const void* p) {
    uint32_t a;
    asm("{ .reg .u64 t; cvta.to.shared.u64 t, %1; cvt.u32.u64 %0, t; }" : "=r"(a) : "l"(p));
    return a;
}
__device__ __forceinline__ void cpasync16(uint32_t dst, const void* src) {
    asm volatile("cp.async.cg.shared.global [%0], [%1], 16;"
                 :: "r"(dst), "l"(__cvta_generic_to_global(src)) : "memory");
}
__device__ __forceinline__ void cpcommit() {
    asm volatile("cp.async.commit_group;" ::: "memory");
}
__device__ __forceinline__ void cpwait0() {
    asm volatile("cp.async.wait_group 0;" ::: "memory");
}
__device__ __forceinline__ void cpwait1() {
    asm volatile("cp.async.wait_group 1;" ::: "memory");
}
__device__ __forceinline__ void ldsm_x4(uint32_t* r, uint32_t addr) {
    asm volatile("ldmatrix.sync.aligned.m8n8.x4.shared.b16 {%0,%1,%2,%3}, [%4];"
                 : "=r"(r[0]), "=r"(r[1]), "=r"(r[2]), "=r"(r[3]) : "r"(addr));
}
__device__ __forceinline__ void ldsm_x2(uint32_t* r, uint32_t addr) {
    asm volatile("ldmatrix.sync.aligned.m8n8.x2.shared.b16 {%0,%1}, [%2];"
                 : "=r"(r[0]), "=r"(r[1]) : "r"(addr));
}
__device__ __forceinline__ void mma16816(float* d, const uint32_t* a, const uint32_t* b) {
    asm volatile(
        "mma.sync.aligned.m16n8k16.row.col.f32.bf16.bf16.f32 "
        "{%0,%1,%2,%3}, {%4,%5,%6,%7}, {%8,%9}, {%0,%1,%2,%3};"
        : "+f"(d[0]), "+f"(d[1]), "+f"(d[2]), "+f"(d[3])
        : "r"(a[0]), "r"(a[1]), "r"(a[2]), "r"(a[3]), "r"(b[0]), "r"(b[1]));
}
// packed fp32x2 FMA: d = a*b + d elementwise on two lanes
__device__ __forceinline__ void ffma2(unsigned long long& d, unsigned long long a,
                                      unsigned long long b) {
    asm("fma.rn.f32x2 %0, %1, %2, %0;" : "+l"(d) : "l"(a), "l"(b));
}
__device__ __forceinline__ float hsum2(unsigned long long v) {
    float2 f = *(float2*)&v;
    return f.x + f.y;
}

// ---------------- kernel 0: repack Whh into k-major packed layout ----------------
__global__ void repack_whh(const float* __restrict__ icWhh,
                           const float* __restrict__ ciWhh) {
    int idx = blockIdx.x * blockDim.x + threadIdx.x;
    if (idx >= NDIR * G * H) return;
    int dir = idx / (G * H);
    int rem = idx % (G * H);
    int g = rem / H;
    int k = rem % H;
    const float* src = (dir < 2) ? (icWhh + (size_t)dir * G * H)
                                 : (ciWhh + (size_t)(dir - 2) * G * H);
    float v = src[(size_t)g * H + k];
    g_wpk[(size_t)dir * G * H + (size_t)(k >> 2) * (G * 4) + g * 4 + (k & 3)] = v;
}

// ---------------- kernel 0b: split data into [ah|al] bf16 rows of 512 ------------
__global__ __launch_bounds__(256) void conv_data(const float* __restrict__ data) {
    size_t i4 = (size_t)blockIdx.x * 256 + threadIdx.x;   // float4 index
    float4 v = ((const float4*)data)[i4];
    size_t m = i4 >> 6;          // 64 float4 per row of 256
    int k = (int)(i4 & 63) * 4;
    __nv_bfloat16 h0 = __float2bfloat16_rn(v.x);
    __nv_bfloat16 h1 = __float2bfloat16_rn(v.y);
    __nv_bfloat16 h2 = __float2bfloat16_rn(v.z);
    __nv_bfloat16 h3 = __float2bfloat16_rn(v.w);
    __nv_bfloat16 l0 = __float2bfloat16_rn(v.x - __bfloat162float(h0));
    __nv_bfloat16 l1 = __float2bfloat16_rn(v.y - __bfloat162float(h1));
    __nv_bfloat16 l2 = __float2bfloat16_rn(v.z - __bfloat162float(h2));
    __nv_bfloat16 l3 = __float2bfloat16_rn(v.w - __bfloat162float(h3));
    ushort4 hv, lv;
    hv.x = __bfloat16_as_ushort(h0); hv.y = __bfloat16_as_ushort(h1);
    hv.z = __bfloat16_as_ushort(h2); hv.w = __bfloat16_as_ushort(h3);
    lv.x = __bfloat16_as_ushort(l0); lv.y = __bfloat16_as_ushort(l1);
    lv.z = __bfloat16_as_ushort(l2); lv.w = __bfloat16_as_ushort(l3);
    __nv_bfloat16* row = g_abf + m * KPA;
    *(ushort4*)&row[k] = hv;               // ah
    *(ushort4*)&row[256 + k] = lv;         // al
}

// ---------------- kernel 0c: split weights into [bh|bh|bl] + folded bias ----------
__global__ __launch_bounds__(256) void conv_w(
    const float* __restrict__ icWih, const float* __restrict__ icBih,
    const float* __restrict__ ciWih, const float* __restrict__ ciBih,
    const float* __restrict__ icBhh, const float* __restrict__ ciBhh) {
    int idx = blockIdx.x * 256 + threadIdx.x;   // n*256 + k
    int n = idx >> 8;
    int k = idx & 255;
    int dir = n / G;
    int g = n - dir * G;
    const float* Wsel = (dir < 2) ? (icWih + (size_t)dir * G * D)
                                  : (ciWih + (size_t)(dir - 2) * G * D);
    const float* Bsel = (dir < 2) ? (icBih + dir * G) : (ciBih + (dir - 2) * G);
    const float* Bhh  = (dir < 2) ? (icBhh + dir * G) : (ciBhh + (dir - 2) * G);
    float x = Wsel[(size_t)g * D + k];
    __nv_bfloat16 hi = __float2bfloat16_rn(x);
    __nv_bfloat16 lo = __float2bfloat16_rn(x - __bfloat162float(hi));
    __nv_bfloat16* row = g_bbf + (size_t)n * KP;
    row[k] = hi;             // bh
    row[256 + k] = hi;       // bh (dup)
    row[512 + k] = lo;       // bl
    if (k == 0) g_bias[n] = Bsel[g] + Bhh[g];   // fold recurrent bias
}

// ---------------- kernel 1: projection GEMM via mma.sync bf16 (HMMA) ------------
// 3-stage cp.async pipeline, 2 CTAs/SM, single sync per K-chunk.
#define BK 32
#define NCH (KP / BK)      // 24
#define LDS_STRIDE 40      // bf16 elems per smem row (32 + 8 pad) -> 80 B
#define STG_B (128 * LDS_STRIDE * 2)        // 10240 B per stage per matrix
#define SMEM_PROJ (3 * STG_B * 2 + 512)     // 61952 B

__global__ __launch_bounds__(256, 2) void proj_hmma() {
    extern __shared__ char psm[];
    uint32_t sA = smem_u32(psm);
    uint32_t sB = sA + 3 * STG_B;
    float* bias_sm = (float*)(psm + 6 * STG_B);

    int tid = threadIdx.x;
    int wid = tid >> 5;
    int lid = tid & 31;
    int wm = wid >> 1;            // 0..3
    int wn = wid & 1;             // 0..1

    int n0 = blockIdx.x * 128;            // 12 N-tiles (fastest -> A reuse in L2)
    size_t m0 = (size_t)blockIdx.y * 128; // 2048 M-tiles

    if (tid < 128) bias_sm[tid] = g_bias[n0 + tid];

    const __nv_bfloat16* Ag = g_abf + m0 * KPA;
    const __nv_bfloat16* Bg = g_bbf + (size_t)n0 * KP;

    int r0 = tid >> 2, s0 = tid & 3;
    int r1 = (tid + 256) >> 2, s1 = (tid + 256) & 3;

    int aRow = wm * 32 + (lid & 15);
    int aCol = (lid >> 4) * 16;
    int bRow = wn * 64 + (lid & 7);
    int bCol = ((lid >> 3) & 1) * 16;

    float acc[2][8][4];
    #pragma unroll
    for (int mi = 0; mi < 2; mi++)
        #pragma unroll
        for (int nj = 0; nj < 8; nj++)
            #pragma unroll
            for (int q = 0; q < 4; q++) acc[mi][nj][q] = 0.0f;

    // chunk c: A k-offset folds the duplicated ah block
    #define AOFF(c) ((((c) < 16) ? (c) : ((c) - 16)) * BK)

    // prologue: stages 0,1 <- chunks 0,1
    #pragma unroll
    for (int c = 0; c < 2; c++) {
        uint32_t dA = sA + c * STG_B;
        uint32_t dB = sB + c * STG_B;
        int ao = AOFF(c), bo = c * BK;
        cpasync16(dA + r0 * 80 + s0 * 16, Ag + (size_t)r0 * KPA + ao + s0 * 8);
        cpasync16(dA + r1 * 80 + s1 * 16, Ag + (size_t)r1 * KPA + ao + s1 * 8);
        cpasync16(dB + r0 * 80 + s0 * 16, Bg + (size_t)r0 * KP + bo + s0 * 8);
        cpasync16(dB + r1 * 80 + s1 * 16, Bg + (size_t)r1 * KP + bo + s1 * 8);
        cpcommit();
    }

    for (int i = 0; i < NCH; i++) {
        if (i == NCH - 1) cpwait0(); else cpwait1();
        __syncthreads();

        // issue next chunk into stage (i+2)%3
        if (i + 2 < NCH) {
            int c = i + 2;
            int st = c % 3;
            uint32_t dA = sA + st * STG_B;
            uint32_t dB = sB + st * STG_B;
            int ao = AOFF(c), bo = c * BK;
            cpasync16(dA + r0 * 80 + s0 * 16, Ag + (size_t)r0 * KPA + ao + s0 * 8);
            cpasync16(dA + r1 * 80 + s1 * 16, Ag + (size_t)r1 * KPA + ao + s1 * 8);
            cpasync16(dB + r0 * 80 + s0 * 16, Bg + (size_t)r0 * KP + bo + s0 * 8);
            cpasync16(dB + r1 * 80 + s1 * 16, Bg + (size_t)r1 * KP + bo + s1 * 8);
            cpcommit();
        } else {
            cpcommit();   // keep group numbering uniform
        }

        uint32_t aBase = sA + (i % 3) * STG_B;
        uint32_t bBase = sB + (i % 3) * STG_B;
        #pragma unroll
        for (int ks = 0; ks < 2; ks++) {
            uint32_t afr[2][4];
            #pragma unroll
            for (int mi = 0; mi < 2; mi++)
                ldsm_x4(afr[mi], aBase + (aRow + mi * 16) * 80 + ks * 32 + aCol);
            uint32_t bfr[8][2];
            #pragma unroll
            for (int nj = 0; nj < 8; nj++)
                ldsm_x2(bfr[nj], bBase + (bRow + nj * 8) * 80 + ks * 32 + bCol);
            #pragma unroll
            for (int mi = 0; mi < 2; mi++)
                #pragma unroll
                for (int nj = 0; nj < 8; nj++)
                    mma16816(acc[mi][nj], afr[mi], bfr[nj]);
        }
        __syncthreads();
    }

    int qr = lid >> 2;
    int qc = (lid & 3) * 2;
    #pragma unroll
    for (int mi = 0; mi < 2; mi++) {
        #pragma unroll
        for (int nj = 0; nj < 8; nj++) {
            int lc = wn * 64 + nj * 8 + qc;
            size_t row = m0 + wm * 32 + mi * 16 + qr;
            float2 v0, v1;
            v0.x = acc[mi][nj][0] + bias_sm[lc];
            v0.y = acc[mi][nj][1] + bias_sm[lc + 1];
            v1.x = acc[mi][nj][2] + bias_sm[lc];
            v1.y = acc[mi][nj][3] + bias_sm[lc + 1];
            *(float2*)&g_xall[row * NTOT + n0 + lc] = v0;
            *(float2*)&g_xall[(row + 8) * NTOT + n0 + lc] = v1;
        }
    }
}

// ---------------- kernel 2: recurrent scan (SMEM-resident W, FFMA2) --------------
#define RT 16
// dynamic smem layout (floats): Wsm[49152] | h[2048] | rh[2048] | Cs[4096]
#define SMEM_SCAN ((49152 + 2048 + 2048 + 4096) * 4)   // 229376 B

__global__ __launch_bounds__(256) void scan_kernel(
    const float* __restrict__ icH0, const float* __restrict__ ciH0,
    float* __restrict__ out) {

    extern __shared__ float sm[];
    float* Wsm = sm;                 // packed [k4][g][4], g in [0,384)
    float* hb  = sm + 49152;         // RT*H
    float* rh  = sm + 49152 + 2048;  // RT*H
    float* Cs  = sm + 49152 + 4096;  // RT rows x 256 cols

    int tid = threadIdx.x;
    int dir = blockIdx.x >> 5;
    int tile = blockIdx.x & 31;
    int b0 = tile * RT;

    const float* h0 = (dir < 2) ? (icH0 + dir * H) : (ciH0 + (dir - 2) * H);

    // load W into SMEM (192 KB), h0 into h
    {
        const float4* wg = (const float4*)(g_wpk + (size_t)dir * G * H);
        float4* Wsm4 = (float4*)Wsm;
        #pragma unroll
        for (int i = 0; i < (G * H / 4) / 256; i++)
            Wsm4[tid + 256 * i] = wg[tid + 256 * i];
        for (int i = tid; i < RT * H; i += 256) hb[i] = h0[i % H];
    }
    __syncthreads();

    const bool backward = (dir & 1);
    const bool is_ci = (dir >= 2);
    const float* xbase = g_xall + (size_t)b0 * T * NTOT + dir * G;
    const size_t rowstride = (size_t)T * NTOT;

    int g2 = tid & 127;
    int r0 = (tid >> 7) * 8;   // 0 or 8

    for (int step = 0; step < T; step++) {
        int t = backward ? (T - 1 - step) : step;
        const float* xt = xbase + (size_t)t * NTOT;

        // prefetch this step's x values into registers (hidden under GEMM1)
        float xz[8], xr[8], xn[8];
        #pragma unroll
        for (int i = 0; i < 8; i++) {
            const float* xrow = xt + (size_t)(r0 + i) * rowstride;
            xz[i] = __ldg(&xrow[g2]);
            xr[i] = __ldg(&xrow[g2 + 128]);
            xn[i] = __ldg(&xrow[g2 + 256]);
        }

        // ---- GEMM1: Cs[r][tid] = sum_k h[r][k] * W_zr[tid][k]  (FFMA2) ----
        {
            unsigned long long acc[RT];
            #pragma unroll
            for (int r = 0; r < RT; r++) acc[r] = 0ull;
            #pragma unroll 4
            for (int k4 = 0; k4 < H / 4; k4++) {
                ulonglong2 w = *(const ulonglong2*)(Wsm + (size_t)(k4 * G + tid) * 4);
                #pragma unroll
                for (int r = 0; r < RT; r++) {
                    ulonglong2 hv = *(const ulonglong2*)(hb + r * H + k4 * 4);
                    ffma2(acc[r], hv.x, w.x);
                    ffma2(acc[r], hv.y, w.y);
                }
            }
            #pragma unroll
            for (int r = 0; r < RT; r++) Cs[r * 256 + tid] = hsum2(acc[r]);
        }
        __syncthreads();

        // ---- gates: z stays in registers; rh = r * h ----
        float z[8];
        #pragma unroll
        for (int i = 0; i < 8; i++) {
            int r = r0 + i;
            float zz = sigm(xz[i] + Cs[r * 256 + g2]);
            float rr = sigm(xr[i] + Cs[r * 256 + g2 + 128]);
            z[i] = zz;
            rh[r * H + g2] = rr * hb[r * H + g2];
        }
        __syncthreads();

        // ---- GEMM2: c2[i] = sum_k rh[r0+i][k] * W_n[g2][k]; update h ----
        {
            unsigned long long acc[8];
            #pragma unroll
            for (int i = 0; i < 8; i++) acc[i] = 0ull;
            #pragma unroll 4
            for (int k4 = 0; k4 < H / 4; k4++) {
                ulonglong2 w = *(const ulonglong2*)(Wsm + (size_t)(k4 * G + 256 + g2) * 4);
                #pragma unroll
                for (int i = 0; i < 8; i++) {
                    ulonglong2 hv = *(const ulonglong2*)(rh + (r0 + i) * H + k4 * 4);
                    ffma2(acc[i], hv.x, w.x);
                    ffma2(acc[i], hv.y, w.y);
                }
            }
            int slot = is_ci ? (dir == 2 ? t + 1 : t - 1) : 0;
            #pragma unroll
            for (int i = 0; i < 8; i++) {
                int rr = r0 + i;
                float nv = tanhf(xn[i] + hsum2(acc[i]));
                float hn = z[i] * hb[rr * H + g2] + (1.0f - z[i]) * nv;
                hn = fminf(CLIPV, fmaxf(-CLIPV, hn));
                hb[rr * H + g2] = hn;
                if (is_ci && slot >= 0 && slot < T) {
                    size_t o = 65536 + (((size_t)(dir - 2) * B + (b0 + rr)) * T + slot) * H + g2;
                    out[o] = hn;
                }
            }
        }
        __syncthreads();
    }

    if (dir < 2) {
        for (int i = tid; i < RT * H; i += 256) {
            int r = i / H, g = i % H;
            g_hfinal[((size_t)dir * B + b0 + r) * H + g] = hb[r * H + g];
        }
    }
}

// ---------------- kernel 3: zero the lag-pad slots of ci ----------------
__global__ void zero_pads(float* __restrict__ out) {
    int b = blockIdx.x;
    int g = threadIdx.x;
    out[65536 + ((size_t)b * T + 0) * H + g] = 0.0f;
    out[65536 + (((size_t)B + b) * T + (T - 1)) * H + g] = 0.0f;
}

// ---------------- kernel 4: final linear -> ic_mean, ic_std ----------------
__global__ void final_linear(const float* __restrict__ Wl,
                             const float* __restrict__ bl,
                             float* __restrict__ out) {
    __shared__ float hsm[2 * H];
    int b = blockIdx.x;
    int j = threadIdx.x;
    hsm[j] = g_hfinal[(size_t)b * H + j];
    hsm[H + j] = g_hfinal[((size_t)B + b) * H + j];
    __syncthreads();

    float acc = bl[j];
    const float4* w = (const float4*)&Wl[(size_t)j * (2 * H)];
    #pragma unroll 8
    for (int k4 = 0; k4 < (2 * H) / 4; k4++) {
        float4 wv = w[k4];
        float4 hv = *(const float4*)&hsm[k4 * 4];
        acc += wv.x * hv.x + wv.y * hv.y + wv.z * hv.z + wv.w * hv.w;
    }
    if (j < 64) out[(size_t)b * 64 + j] = acc;
    else out[32768 + (size_t)b * 64 + (j - 64)] = expf(acc);
}

// ---------------- launch ----------------
extern "C" void kernel_launch(void* const* d_in, const int* in_sizes, int n_in,
                              void* d_out, int out_size) {
    const float* data   = (const float*)d_in[0];
    const float* ic_h0  = (const float*)d_in[1];
    const float* ci_h0  = (const float*)d_in[2];
    const float* ic_Wih = (const float*)d_in[3];
    const float* ic_bih = (const float*)d_in[4];
    const float* ic_Whh = (const float*)d_in[5];
    const float* ic_bhh = (const float*)d_in[6];
    const float* ci_Wih = (const float*)d_in[7];
    const float* ci_bih = (const float*)d_in[8];
    const float* ci_Whh = (const float*)d_in[9];
    const float* ci_bhh = (const float*)d_in[10];
    const float* Wl     = (const float*)d_in[11];
    const float* bl     = (const float*)d_in[12];
    float* out = (float*)d_out;

    cudaFuncSetAttribute(scan_kernel, cudaFuncAttributeMaxDynamicSharedMemorySize, SMEM_SCAN);
    cudaFuncSetAttribute(proj_hmma, cudaFuncAttributeMaxDynamicSharedMemorySize, SMEM_PROJ);

    repack_whh<<<(NDIR * G * H + 255) / 256, 256>>>(ic_Whh, ci_Whh);
    conv_data<<<(int)((size_t)B * T * D / 4 / 256), 256>>>(data);
    conv_w<<<NTOT, 256>>>(ic_Wih, ic_bih, ci_Wih, ci_bih, ic_bhh, ci_bhh);

    dim3 pgrid(NTOT / 128, B * T / 128);   // 12 x 2048
    proj_hmma<<<pgrid, 256, SMEM_PROJ>>>();

    scan_kernel<<<NDIR * (B / RT), 256, SMEM_SCAN>>>(ic_h0, ci_h0, out);

    zero_pads<<<B, H>>>(out);
    final_linear<<<B, H>>>(Wl, bl, out);
}

// round 7
// speedup vs baseline: 2.8862x; 1.1176x over previous
#include <cuda_runtime.h>
#include <cuda_bf16.h>
#include <cuda_fp16.h>
#include <stdint.h>
#include <math.h>

#define B 512
#define T 512
#define D 256
#define H 128        // IC_ENC == CI_ENC == 128
#define G 384        // 3*H
#define NDIR 4       // 0=ic_fwd, 1=ic_bwd, 2=ci_fwd, 3=ci_bwd
#define CLIPV 5.0f
#define KP 512       // logical K': [ah|al] x [bh|bh]
#define KPA 512      // stored A width: [ah|al]
#define KPB 256      // stored B width: [bh] (chunks >=4 re-read)
#define NTOT (NDIR * G)   // 1536

// ---------------- device scratch (no runtime allocation allowed) ----------------
__device__ float g_xall[(size_t)B * T * NTOT];              // 1.61 GB
__device__ float g_wpk[NDIR * G * H];                       // packed Whh
__device__ float g_hfinal[2 * B * H];
__device__ __half g_abf[(size_t)B * T * KPA];               // A'' fp16 hi/lo, 268 MB
__device__ __half g_bbf[(size_t)NTOT * KPB];                // B'' fp16 hi
__device__ float g_bias[NTOT];                              // bih + bhh (folded)

// ---------------- helpers ----------------
__device__ __forceinline__ float sigm(float x) {
    return 1.0f / (1.0f + __expf(-x));
}
__device__ __forceinline__ uint32_t smem_u32(const void* p) {
    uint32_t a;
    asm("{ .reg .u64 t; cvta.to.shared.u64 t, %1; cvt.u32.u64 %0, t; }" : "=r"(a) : "l"(p));
    return a;
}
__device__ __forceinline__ void cpasync16(uint32_t dst, const void* src) {
    asm volatile("cp.async.cg.shared.global [%0], [%1], 16;"
                 :: "r"(dst), "l"(__cvta_generic_to_global(src)) : "memory");
}
__device__ __forceinline__ void cpcommit() {
    asm volatile("cp.async.commit_group;" ::: "memory");
}
__device__ __forceinline__ void cpwait0() {
    asm volatile("cp.async.wait_group 0;" ::: "memory");
}
__device__ __forceinline__ void cpwait1() {
    asm volatile("cp.async.wait_group 1;" ::: "memory");
}
__device__ __forceinline__ void ldsm_x4(uint32_t* r, uint32_t addr) {
    asm volatile("ldmatrix.sync.aligned.m8n8.x4.shared.b16 {%0,%1,%2,%3}, [%4];"
                 : "=r"(r[0]), "=r"(r[1]), "=r"(r[2]), "=r"(r[3]) : "r"(addr));
}
__device__ __forceinline__ void ldsm_x2(uint32_t* r, uint32_t addr) {
    asm volatile("ldmatrix.sync.aligned.m8n8.x2.shared.b16 {%0,%1}, [%2];"
                 : "=r"(r[0]), "=r"(r[1]) : "r"(addr));
}
__device__ __forceinline__ void mma16816(float* d, const uint32_t* a, const uint32_t* b) {
    asm volatile(
        "mma.sync.aligned.m16n8k16.row.col.f32.f16.f16.f32 "
        "{%0,%1,%2,%3}, {%4,%5,%6,%7}, {%8,%9}, {%0,%1,%2,%3};"
        : "+f"(d[0]), "+f"(d[1]), "+f"(d[2]), "+f"(d[3])
        : "r"(a[0]), "r"(a[1]), "r"(a[2]), "r"(a[3]), "r"(b[0]), "r"(b[1]));
}
// packed fp32x2 FMA: d = a*b + d elementwise on two lanes
__device__ __forceinline__ void ffma2(unsigned long long& d, unsigned long long a,
                                      unsigned long long b) {
    asm("fma.rn.f32x2 %0, %1, %2, %0;" : "+l"(d) : "l"(a), "l"(b));
}
__device__ __forceinline__ float hsum2(unsigned long long v) {
    float2 f = *(float2*)&v;
    return f.x + f.y;
}

// ---------------- kernel 0: repack Whh into k-major packed layout ----------------
__global__ void repack_whh(const float* __restrict__ icWhh,
                           const float* __restrict__ ciWhh) {
    int idx = blockIdx.x * blockDim.x + threadIdx.x;
    if (idx >= NDIR * G * H) return;
    int dir = idx / (G * H);
    int rem = idx % (G * H);
    int g = rem / H;
    int k = rem % H;
    const float* src = (dir < 2) ? (icWhh + (size_t)dir * G * H)
                                 : (ciWhh + (size_t)(dir - 2) * G * H);
    float v = src[(size_t)g * H + k];
    g_wpk[(size_t)dir * G * H + (size_t)(k >> 2) * (G * 4) + g * 4 + (k & 3)] = v;
}

// ---------------- kernel 0b: split data into [ah|al] fp16 rows of 512 ------------
__global__ __launch_bounds__(256) void conv_data(const float* __restrict__ data) {
    size_t i4 = (size_t)blockIdx.x * 256 + threadIdx.x;   // float4 index
    float4 v = ((const float4*)data)[i4];
    size_t m = i4 >> 6;          // 64 float4 per row of 256
    int k = (int)(i4 & 63) * 4;
    __half h0 = __float2half_rn(v.x);
    __half h1 = __float2half_rn(v.y);
    __half h2 = __float2half_rn(v.z);
    __half h3 = __float2half_rn(v.w);
    __half l0 = __float2half_rn(v.x - __half2float(h0));
    __half l1 = __float2half_rn(v.y - __half2float(h1));
    __half l2 = __float2half_rn(v.z - __half2float(h2));
    __half l3 = __float2half_rn(v.w - __half2float(h3));
    ushort4 hv, lv;
    hv.x = __half_as_ushort(h0); hv.y = __half_as_ushort(h1);
    hv.z = __half_as_ushort(h2); hv.w = __half_as_ushort(h3);
    lv.x = __half_as_ushort(l0); lv.y = __half_as_ushort(l1);
    lv.z = __half_as_ushort(l2); lv.w = __half_as_ushort(l3);
    __half* row = g_abf + m * KPA;
    *(ushort4*)&row[k] = hv;               // ah
    *(ushort4*)&row[256 + k] = lv;         // al
}

// ---------------- kernel 0c: weights -> fp16 hi + folded bias --------------------
__global__ __launch_bounds__(256) void conv_w(
    const float* __restrict__ icWih, const float* __restrict__ icBih,
    const float* __restrict__ ciWih, const float* __restrict__ ciBih,
    const float* __restrict__ icBhh, const float* __restrict__ ciBhh) {
    int idx = blockIdx.x * 256 + threadIdx.x;   // n*256 + k
    int n = idx >> 8;
    int k = idx & 255;
    int dir = n / G;
    int g = n - dir * G;
    const float* Wsel = (dir < 2) ? (icWih + (size_t)dir * G * D)
                                  : (ciWih + (size_t)(dir - 2) * G * D);
    const float* Bsel = (dir < 2) ? (icBih + dir * G) : (ciBih + (dir - 2) * G);
    const float* Bhh  = (dir < 2) ? (icBhh + dir * G) : (ciBhh + (dir - 2) * G);
    float x = Wsel[(size_t)g * D + k];
    g_bbf[(size_t)n * KPB + k] = __float2half_rn(x);
    if (k == 0) g_bias[n] = Bsel[g] + Bhh[g];   // fold recurrent bias
}

// ---------------- kernel 1: projection GEMM via mma.sync fp16 (HMMA) ------------
// K'=512 (2-term fp16 split). 3-stage cp.async pipeline, BK=64, 2 CTAs/SM.
#define BK 64
#define NCH (KP / BK)      // 8
#define LDS_STRIDE 72      // fp16 elems per smem row (64 + 8 pad) -> 144 B
#define STG_B (128 * LDS_STRIDE * 2)        // 18432 B per stage per matrix
#define SMEM_PROJ (3 * STG_B * 2 + 512)     // 111104 B

__global__ __launch_bounds__(256, 2) void proj_hmma() {
    extern __shared__ char psm[];
    uint32_t sA = smem_u32(psm);
    uint32_t sB = sA + 3 * STG_B;
    float* bias_sm = (float*)(psm + 6 * STG_B);

    int tid = threadIdx.x;
    int wid = tid >> 5;
    int lid = tid & 31;
    int wm = wid >> 1;            // 0..3
    int wn = wid & 1;             // 0..1

    int n0 = blockIdx.x * 128;            // 12 N-tiles (fastest -> A reuse in L2)
    size_t m0 = (size_t)blockIdx.y * 128; // 2048 M-tiles

    if (tid < 128) bias_sm[tid] = g_bias[n0 + tid];

    const __half* Ag = g_abf + m0 * KPA;
    const __half* Bg = g_bbf + (size_t)n0 * KPB;

    int aRow = wm * 32 + (lid & 15);
    int aCol = (lid >> 4) * 16;
    int bRow = wn * 64 + (lid & 7);
    int bCol = ((lid >> 3) & 1) * 16;

    float acc[2][8][4];
    #pragma unroll
    for (int mi = 0; mi < 2; mi++)
        #pragma unroll
        for (int nj = 0; nj < 8; nj++)
            #pragma unroll
            for (int q = 0; q < 4; q++) acc[mi][nj][q] = 0.0f;

    // B k-offset folds the duplicated bh block (storage is 256 wide)
    #define BOFF(c) ((((c) < 4) ? (c) : ((c) - 4)) * BK)

    // tile loader: 1024 16B-chunks per matrix per chunk, 4 per thread
    #define LOAD_CHUNK(stg, c) do {                                            \
        uint32_t dA = sA + (stg) * STG_B;                                      \
        uint32_t dB = sB + (stg) * STG_B;                                      \
        int ao = (c) * BK, bo = BOFF(c);                                       \
        _Pragma("unroll")                                                      \
        for (int l = 0; l < 4; l++) {                                          \
            int idx = tid + 256 * l;                                           \
            int row = idx >> 3;                                                \
            int c16 = idx & 7;                                                 \
            cpasync16(dA + row * 144 + c16 * 16,                               \
                      Ag + (size_t)row * KPA + ao + c16 * 8);                  \
            cpasync16(dB + row * 144 + c16 * 16,                               \
                      Bg + (size_t)row * KPB + bo + c16 * 8);                  \
        }                                                                      \
        cpcommit();                                                            \
    } while (0)

    LOAD_CHUNK(0, 0);
    LOAD_CHUNK(1, 1);

    for (int i = 0; i < NCH; i++) {
        if (i == NCH - 1) cpwait0(); else cpwait1();
        __syncthreads();

        if (i + 2 < NCH) {
            LOAD_CHUNK((i + 2) % 3, i + 2);
        } else {
            cpcommit();   // keep group numbering uniform
        }

        uint32_t aBase = sA + (i % 3) * STG_B;
        uint32_t bBase = sB + (i % 3) * STG_B;
        #pragma unroll
        for (int ks = 0; ks < 4; ks++) {
            uint32_t afr[2][4];
            #pragma unroll
            for (int mi = 0; mi < 2; mi++)
                ldsm_x4(afr[mi], aBase + (aRow + mi * 16) * 144 + ks * 32 + aCol);
            uint32_t bfr[8][2];
            #pragma unroll
            for (int nj = 0; nj < 8; nj++)
                ldsm_x2(bfr[nj], bBase + (bRow + nj * 8) * 144 + ks * 32 + bCol);
            #pragma unroll
            for (int mi = 0; mi < 2; mi++)
                #pragma unroll
                for (int nj = 0; nj < 8; nj++)
                    mma16816(acc[mi][nj], afr[mi], bfr[nj]);
        }
        __syncthreads();
    }

    int qr = lid >> 2;
    int qc = (lid & 3) * 2;
    #pragma unroll
    for (int mi = 0; mi < 2; mi++) {
        #pragma unroll
        for (int nj = 0; nj < 8; nj++) {
            int lc = wn * 64 + nj * 8 + qc;
            size_t row = m0 + wm * 32 + mi * 16 + qr;
            float2 v0, v1;
            v0.x = acc[mi][nj][0] + bias_sm[lc];
            v0.y = acc[mi][nj][1] + bias_sm[lc + 1];
            v1.x = acc[mi][nj][2] + bias_sm[lc];
            v1.y = acc[mi][nj][3] + bias_sm[lc + 1];
            *(float2*)&g_xall[row * NTOT + n0 + lc] = v0;
            *(float2*)&g_xall[(row + 8) * NTOT + n0 + lc] = v1;
        }
    }
}

// ---------------- kernel 2: recurrent scan (SMEM-resident W, FFMA2) --------------
#define RT 16
// dynamic smem layout (floats): Wsm[49152] | h[2048] | rh[2048] | Cs[4096]
#define SMEM_SCAN ((49152 + 2048 + 2048 + 4096) * 4)   // 229376 B

__global__ __launch_bounds__(256) void scan_kernel(
    const float* __restrict__ icH0, const float* __restrict__ ciH0,
    float* __restrict__ out) {

    extern __shared__ float sm[];
    float* Wsm = sm;                 // packed [k4][g][4], g in [0,384)
    float* hb  = sm + 49152;         // RT*H
    float* rh  = sm + 49152 + 2048;  // RT*H
    float* Cs  = sm + 49152 + 4096;  // RT rows x 256 cols

    int tid = threadIdx.x;
    int dir = blockIdx.x >> 5;
    int tile = blockIdx.x & 31;
    int b0 = tile * RT;

    const float* h0 = (dir < 2) ? (icH0 + dir * H) : (ciH0 + (dir - 2) * H);

    // load W into SMEM (192 KB), h0 into h
    {
        const float4* wg = (const float4*)(g_wpk + (size_t)dir * G * H);
        float4* Wsm4 = (float4*)Wsm;
        #pragma unroll
        for (int i = 0; i < (G * H / 4) / 256; i++)
            Wsm4[tid + 256 * i] = wg[tid + 256 * i];
        for (int i = tid; i < RT * H; i += 256) hb[i] = h0[i % H];
    }
    __syncthreads();

    const bool backward = (dir & 1);
    const bool is_ci = (dir >= 2);
    const float* xbase = g_xall + (size_t)b0 * T * NTOT + dir * G;
    const size_t rowstride = (size_t)T * NTOT;

    int g2 = tid & 127;
    int r0 = (tid >> 7) * 8;   // 0 or 8

    for (int step = 0; step < T; step++) {
        int t = backward ? (T - 1 - step) : step;
        const float* xt = xbase + (size_t)t * NTOT;

        // prefetch this step's x values into registers (hidden under GEMM1)
        float xz[8], xr[8], xn[8];
        #pragma unroll
        for (int i = 0; i < 8; i++) {
            const float* xrow = xt + (size_t)(r0 + i) * rowstride;
            xz[i] = __ldg(&xrow[g2]);
            xr[i] = __ldg(&xrow[g2 + 128]);
            xn[i] = __ldg(&xrow[g2 + 256]);
        }

        // ---- GEMM1: Cs[r][tid] = sum_k h[r][k] * W_zr[tid][k]  (FFMA2) ----
        {
            unsigned long long acc[RT];
            #pragma unroll
            for (int r = 0; r < RT; r++) acc[r] = 0ull;
            #pragma unroll 4
            for (int k4 = 0; k4 < H / 4; k4++) {
                ulonglong2 w = *(const ulonglong2*)(Wsm + (size_t)(k4 * G + tid) * 4);
                #pragma unroll
                for (int r = 0; r < RT; r++) {
                    ulonglong2 hv = *(const ulonglong2*)(hb + r * H + k4 * 4);
                    ffma2(acc[r], hv.x, w.x);
                    ffma2(acc[r], hv.y, w.y);
                }
            }
            #pragma unroll
            for (int r = 0; r < RT; r++) Cs[r * 256 + tid] = hsum2(acc[r]);
        }
        __syncthreads();

        // ---- gates: z stays in registers; rh = r * h ----
        float z[8];
        #pragma unroll
        for (int i = 0; i < 8; i++) {
            int r = r0 + i;
            float zz = sigm(xz[i] + Cs[r * 256 + g2]);
            float rr = sigm(xr[i] + Cs[r * 256 + g2 + 128]);
            z[i] = zz;
            rh[r * H + g2] = rr * hb[r * H + g2];
        }
        __syncthreads();

        // ---- GEMM2: c2[i] = sum_k rh[r0+i][k] * W_n[g2][k]; update h ----
        {
            unsigned long long acc[8];
            #pragma unroll
            for (int i = 0; i < 8; i++) acc[i] = 0ull;
            #pragma unroll 4
            for (int k4 = 0; k4 < H / 4; k4++) {
                ulonglong2 w = *(const ulonglong2*)(Wsm + (size_t)(k4 * G + 256 + g2) * 4);
                #pragma unroll
                for (int i = 0; i < 8; i++) {
                    ulonglong2 hv = *(const ulonglong2*)(rh + (r0 + i) * H + k4 * 4);
                    ffma2(acc[i], hv.x, w.x);
                    ffma2(acc[i], hv.y, w.y);
                }
            }
            int slot = is_ci ? (dir == 2 ? t + 1 : t - 1) : 0;
            #pragma unroll
            for (int i = 0; i < 8; i++) {
                int rr = r0 + i;
                float nv = tanhf(xn[i] + hsum2(acc[i]));
                float hn = z[i] * hb[rr * H + g2] + (1.0f - z[i]) * nv;
                hn = fminf(CLIPV, fmaxf(-CLIPV, hn));
                hb[rr * H + g2] = hn;
                if (is_ci && slot >= 0 && slot < T) {
                    size_t o = 65536 + (((size_t)(dir - 2) * B + (b0 + rr)) * T + slot) * H + g2;
                    out[o] = hn;
                }
            }
        }
        __syncthreads();
    }

    if (dir < 2) {
        for (int i = tid; i < RT * H; i += 256) {
            int r = i / H, g = i % H;
            g_hfinal[((size_t)dir * B + b0 + r) * H + g] = hb[r * H + g];
        }
    }
}

// ---------------- kernel 3: zero the lag-pad slots of ci ----------------
__global__ void zero_pads(float* __restrict__ out) {
    int b = blockIdx.x;
    int g = threadIdx.x;
    out[65536 + ((size_t)b * T + 0) * H + g] = 0.0f;
    out[65536 + (((size_t)B + b) * T + (T - 1)) * H + g] = 0.0f;
}

// ---------------- kernel 4: final linear -> ic_mean, ic_std ----------------
__global__ void final_linear(const float* __restrict__ Wl,
                             const float* __restrict__ bl,
                             float* __restrict__ out) {
    __shared__ float hsm[2 * H];
    int b = blockIdx.x;
    int j = threadIdx.x;
    hsm[j] = g_hfinal[(size_t)b * H + j];
    hsm[H + j] = g_hfinal[((size_t)B + b) * H + j];
    __syncthreads();

    float acc = bl[j];
    const float4* w = (const float4*)&Wl[(size_t)j * (2 * H)];
    #pragma unroll 8
    for (int k4 = 0; k4 < (2 * H) / 4; k4++) {
        float4 wv = w[k4];
        float4 hv = *(const float4*)&hsm[k4 * 4];
        acc += wv.x * hv.x + wv.y * hv.y + wv.z * hv.z + wv.w * hv.w;
    }
    if (j < 64) out[(size_t)b * 64 + j] = acc;
    else out[32768 + (size_t)b * 64 + (j - 64)] = expf(acc);
}

// ---------------- launch ----------------
extern "C" void kernel_launch(void* const* d_in, const int* in_sizes, int n_in,
                              void* d_out, int out_size) {
    const float* data   = (const float*)d_in[0];
    const float* ic_h0  = (const float*)d_in[1];
    const float* ci_h0  = (const float*)d_in[2];
    const float* ic_Wih = (const float*)d_in[3];
    const float* ic_bih = (const float*)d_in[4];
    const float* ic_Whh = (const float*)d_in[5];
    const float* ic_bhh = (const float*)d_in[6];
    const float* ci_Wih = (const float*)d_in[7];
    const float* ci_bih = (const float*)d_in[8];
    const float* ci_Whh = (const float*)d_in[9];
    const float* ci_bhh = (const float*)d_in[10];
    const float* Wl     = (const float*)d_in[11];
    const float* bl     = (const float*)d_in[12];
    float* out = (float*)d_out;

    cudaFuncSetAttribute(scan_kernel, cudaFuncAttributeMaxDynamicSharedMemorySize, SMEM_SCAN);
    cudaFuncSetAttribute(proj_hmma, cudaFuncAttributeMaxDynamicSharedMemorySize, SMEM_PROJ);

    repack_whh<<<(NDIR * G * H + 255) / 256, 256>>>(ic_Whh, ci_Whh);
    conv_data<<<(int)((size_t)B * T * D / 4 / 256), 256>>>(data);
    conv_w<<<NTOT, 256>>>(ic_Wih, ic_bih, ci_Wih, ci_bih, ic_bhh, ci_bhh);

    dim3 pgrid(NTOT / 128, B * T / 128);   // 12 x 2048
    proj_hmma<<<pgrid, 256, SMEM_PROJ>>>();

    scan_kernel<<<NDIR * (B / RT), 256, SMEM_SCAN>>>(ic_h0, ci_h0, out);

    zero_pads<<<B, H>>>(out);
    final_linear<<<B, H>>>(Wl, bl, out);
}

// round 8
// speedup vs baseline: 3.2732x; 1.1341x over previous
#include <cuda_runtime.h>
#include <cuda_bf16.h>
#include <cuda_fp16.h>
#include <stdint.h>
#include <math.h>

#define B 512
#define T 512
#define D 256
#define H 128        // IC_ENC == CI_ENC == 128
#define G 384        // 3*H
#define NDIR 4       // 0=ic_fwd, 1=ic_bwd, 2=ci_fwd, 3=ci_bwd
#define CLIPV 5.0f
#define KP 512       // logical K': [ah|al] x [bh|bh]
#define KPA 512      // stored A width: [ah|al]
#define KPB 256      // stored B width: [bh] (chunks >=4 re-read)
#define NTOT (NDIR * G)   // 1536

// ---------------- device scratch (no runtime allocation allowed) ----------------
__device__ float g_xall[(size_t)B * T * NTOT];              // 1.61 GB
__device__ float g_wpk[NDIR * G * H];                       // packed Whh
__device__ float g_hfinal[2 * B * H];
__device__ __half g_abf[(size_t)B * T * KPA];               // A'' fp16 hi/lo, 268 MB
__device__ __half g_bbf[(size_t)NTOT * KPB];                // B'' fp16 hi
__device__ float g_bias[NTOT];                              // bih + bhh (folded)

// ---------------- helpers ----------------
__device__ __forceinline__ float sigm(float x) {
    return 1.0f / (1.0f + __expf(-x));
}
__device__ __forceinline__ uint32_t smem_u32(const void* p) {
    uint32_t a;
    asm("{ .reg .u64 t; cvta.to.shared.u64 t, %1; cvt.u32.u64 %0, t; }" : "=r"(a) : "l"(p));
    return a;
}
__device__ __forceinline__ void cpasync16(uint32_t dst, const void* src) {
    asm volatile("cp.async.cg.shared.global [%0], [%1], 16;"
                 :: "r"(dst), "l"(__cvta_generic_to_global(src)) : "memory");
}
__device__ __forceinline__ void cpcommit() {
    asm volatile("cp.async.commit_group;" ::: "memory");
}
__device__ __forceinline__ void cpwait0() {
    asm volatile("cp.async.wait_group 0;" ::: "memory");
}
__device__ __forceinline__ void cpwait1() {
    asm volatile("cp.async.wait_group 1;" ::: "memory");
}
__device__ __forceinline__ void ldsm_x4(uint32_t* r, uint32_t addr) {
    asm volatile("ldmatrix.sync.aligned.m8n8.x4.shared.b16 {%0,%1,%2,%3}, [%4];"
                 : "=r"(r[0]), "=r"(r[1]), "=r"(r[2]), "=r"(r[3]) : "r"(addr));
}
__device__ __forceinline__ void mma16816(float* d, const uint32_t* a, const uint32_t* b) {
    asm volatile(
        "mma.sync.aligned.m16n8k16.row.col.f32.f16.f16.f32 "
        "{%0,%1,%2,%3}, {%4,%5,%6,%7}, {%8,%9}, {%0,%1,%2,%3};"
        : "+f"(d[0]), "+f"(d[1]), "+f"(d[2]), "+f"(d[3])
        : "r"(a[0]), "r"(a[1]), "r"(a[2]), "r"(a[3]), "r"(b[0]), "r"(b[1]));
}
// packed fp32x2 FMA: d = a*b + d elementwise on two lanes
__device__ __forceinline__ void ffma2(unsigned long long& d, unsigned long long a,
                                      unsigned long long b) {
    asm("fma.rn.f32x2 %0, %1, %2, %0;" : "+l"(d) : "l"(a), "l"(b));
}
__device__ __forceinline__ float hsum2(unsigned long long v) {
    float2 f = *(float2*)&v;
    return f.x + f.y;
}

// ---------------- kernel 0: repack Whh into k-major packed layout ----------------
__global__ void repack_whh(const float* __restrict__ icWhh,
                           const float* __restrict__ ciWhh) {
    int idx = blockIdx.x * blockDim.x + threadIdx.x;
    if (idx >= NDIR * G * H) return;
    int dir = idx / (G * H);
    int rem = idx % (G * H);
    int g = rem / H;
    int k = rem % H;
    const float* src = (dir < 2) ? (icWhh + (size_t)dir * G * H)
                                 : (ciWhh + (size_t)(dir - 2) * G * H);
    float v = src[(size_t)g * H + k];
    g_wpk[(size_t)dir * G * H + (size_t)(k >> 2) * (G * 4) + g * 4 + (k & 3)] = v;
}

// ---------------- kernel 0b: split data into [ah|al] fp16 rows of 512 ------------
__global__ __launch_bounds__(256) void conv_data(const float* __restrict__ data) {
    size_t i4 = (size_t)blockIdx.x * 256 + threadIdx.x;   // float4 index
    float4 v = ((const float4*)data)[i4];
    size_t m = i4 >> 6;          // 64 float4 per row of 256
    int k = (int)(i4 & 63) * 4;
    __half h0 = __float2half_rn(v.x);
    __half h1 = __float2half_rn(v.y);
    __half h2 = __float2half_rn(v.z);
    __half h3 = __float2half_rn(v.w);
    __half l0 = __float2half_rn(v.x - __half2float(h0));
    __half l1 = __float2half_rn(v.y - __half2float(h1));
    __half l2 = __float2half_rn(v.z - __half2float(h2));
    __half l3 = __float2half_rn(v.w - __half2float(h3));
    ushort4 hv, lv;
    hv.x = __half_as_ushort(h0); hv.y = __half_as_ushort(h1);
    hv.z = __half_as_ushort(h2); hv.w = __half_as_ushort(h3);
    lv.x = __half_as_ushort(l0); lv.y = __half_as_ushort(l1);
    lv.z = __half_as_ushort(l2); lv.w = __half_as_ushort(l3);
    __half* row = g_abf + m * KPA;
    *(ushort4*)&row[k] = hv;               // ah
    *(ushort4*)&row[256 + k] = lv;         // al
}

// ---------------- kernel 0c: weights -> fp16 hi + folded bias --------------------
__global__ __launch_bounds__(256) void conv_w(
    const float* __restrict__ icWih, const float* __restrict__ icBih,
    const float* __restrict__ ciWih, const float* __restrict__ ciBih,
    const float* __restrict__ icBhh, const float* __restrict__ ciBhh) {
    int idx = blockIdx.x * 256 + threadIdx.x;   // n*256 + k
    int n = idx >> 8;
    int k = idx & 255;
    int dir = n / G;
    int g = n - dir * G;
    const float* Wsel = (dir < 2) ? (icWih + (size_t)dir * G * D)
                                  : (ciWih + (size_t)(dir - 2) * G * D);
    const float* Bsel = (dir < 2) ? (icBih + dir * G) : (ciBih + (dir - 2) * G);
    const float* Bhh  = (dir < 2) ? (icBhh + dir * G) : (ciBhh + (dir - 2) * G);
    float x = Wsel[(size_t)g * D + k];
    g_bbf[(size_t)n * KPB + k] = __float2half_rn(x);
    if (k == 0) g_bias[n] = Bsel[g] + Bhh[g];   // fold recurrent bias
}

// ---------------- kernel 1: projection GEMM via mma.sync fp16 (HMMA) ------------
// K'=512 (2-term fp16 split). 3-stage cp.async pipeline, BK=64, 2 CTAs/SM,
// single __syncthreads per K-chunk, B fragments via ldsm_x4 pairs.
#define BK 64
#define NCH (KP / BK)      // 8
#define LDS_STRIDE 72      // fp16 elems per smem row (64 + 8 pad) -> 144 B
#define STG_B (128 * LDS_STRIDE * 2)        // 18432 B per stage per matrix
#define SMEM_PROJ (3 * STG_B * 2 + 512)     // 111104 B

__global__ __launch_bounds__(256, 2) void proj_hmma() {
    extern __shared__ char psm[];
    uint32_t sA = smem_u32(psm);
    uint32_t sB = sA + 3 * STG_B;
    float* bias_sm = (float*)(psm + 6 * STG_B);

    int tid = threadIdx.x;
    int wid = tid >> 5;
    int lid = tid & 31;
    int wm = wid >> 1;            // 0..3
    int wn = wid & 1;             // 0..1

    int n0 = blockIdx.x * 128;            // 12 N-tiles (fastest -> A reuse in L2)
    size_t m0 = (size_t)blockIdx.y * 128; // 2048 M-tiles

    if (tid < 128) bias_sm[tid] = g_bias[n0 + tid];

    const __half* Ag = g_abf + m0 * KPA;
    const __half* Bg = g_bbf + (size_t)n0 * KPB;

    int aRow = wm * 32 + (lid & 15);
    int aCol = (lid >> 4) * 16;
    // ldsm_x4 B addressing: lanes 0-7 rows 0-7 col0, 8-15 rows 0-7 col16,
    // 16-23 rows 8-15 col0, 24-31 rows 8-15 col16
    int bRow4 = wn * 64 + ((lid >> 4) * 8) + (lid & 7);
    int bCol4 = ((lid >> 3) & 1) * 16;

    float acc[2][8][4];
    #pragma unroll
    for (int mi = 0; mi < 2; mi++)
        #pragma unroll
        for (int nj = 0; nj < 8; nj++)
            #pragma unroll
            for (int q = 0; q < 4; q++) acc[mi][nj][q] = 0.0f;

    // B k-offset folds the duplicated bh block (storage is 256 wide)
    #define BOFF(c) ((((c) < 4) ? (c) : ((c) - 4)) * BK)

    #define LOAD_CHUNK(stg, c) do {                                            \
        uint32_t dA = sA + (stg) * STG_B;                                      \
        uint32_t dB = sB + (stg) * STG_B;                                      \
        int ao = (c) * BK, bo = BOFF(c);                                       \
        _Pragma("unroll")                                                      \
        for (int l = 0; l < 4; l++) {                                          \
            int idx = tid + 256 * l;                                           \
            int row = idx >> 3;                                                \
            int c16 = idx & 7;                                                 \
            cpasync16(dA + row * 144 + c16 * 16,                               \
                      Ag + (size_t)row * KPA + ao + c16 * 8);                  \
            cpasync16(dB + row * 144 + c16 * 16,                               \
                      Bg + (size_t)row * KPB + bo + c16 * 8);                  \
        }                                                                      \
        cpcommit();                                                            \
    } while (0)

    LOAD_CHUNK(0, 0);
    LOAD_CHUNK(1, 1);

    for (int i = 0; i < NCH; i++) {
        if (i == NCH - 1) cpwait0(); else cpwait1();
        __syncthreads();

        if (i + 2 < NCH) LOAD_CHUNK((i + 2) % 3, i + 2);

        uint32_t aBase = sA + (i % 3) * STG_B;
        uint32_t bBase = sB + (i % 3) * STG_B;
        #pragma unroll
        for (int ks = 0; ks < 4; ks++) {
            uint32_t afr[2][4];
            #pragma unroll
            for (int mi = 0; mi < 2; mi++)
                ldsm_x4(afr[mi], aBase + (aRow + mi * 16) * 144 + ks * 32 + aCol);
            uint32_t bfr[8][2];
            #pragma unroll
            for (int nj2 = 0; nj2 < 4; nj2++) {
                uint32_t q[4];
                ldsm_x4(q, bBase + (bRow4 + nj2 * 16) * 144 + ks * 32 + bCol4);
                bfr[nj2 * 2][0] = q[0]; bfr[nj2 * 2][1] = q[1];
                bfr[nj2 * 2 + 1][0] = q[2]; bfr[nj2 * 2 + 1][1] = q[3];
            }
            #pragma unroll
            for (int mi = 0; mi < 2; mi++)
                #pragma unroll
                for (int nj = 0; nj < 8; nj++)
                    mma16816(acc[mi][nj], afr[mi], bfr[nj]);
        }
        // no trailing barrier: stage reuse is protected by the barrier at the
        // top of the iteration that overwrites it (3-stage pipeline invariant)
    }

    int qr = lid >> 2;
    int qc = (lid & 3) * 2;
    #pragma unroll
    for (int mi = 0; mi < 2; mi++) {
        #pragma unroll
        for (int nj = 0; nj < 8; nj++) {
            int lc = wn * 64 + nj * 8 + qc;
            size_t row = m0 + wm * 32 + mi * 16 + qr;
            float2 v0, v1;
            v0.x = acc[mi][nj][0] + bias_sm[lc];
            v0.y = acc[mi][nj][1] + bias_sm[lc + 1];
            v1.x = acc[mi][nj][2] + bias_sm[lc];
            v1.y = acc[mi][nj][3] + bias_sm[lc + 1];
            *(float2*)&g_xall[row * NTOT + n0 + lc] = v0;
            *(float2*)&g_xall[(row + 8) * NTOT + n0 + lc] = v1;
        }
    }
}

// ---------------- kernel 2: recurrent scan -----------------------------------
// Multicast-friendly lane mapping: lane = rg(4) x sub(8).
// Thread owns rows r = rg*4+m (m 0..3). GEMM1 cols j = w*32 + l*8 + sub (l 0..3),
// GEMM2/gates cols g = w*16 + l*8 + sub (l 0..1).
// XOR bank swizzle on hb/rh/Cs column index: c ^ (rg(r) << 3).
#define RT 16
#define SMEM_SCAN ((49152 + 2048 + 2048 + 4096) * 4)   // 229376 B

__global__ __launch_bounds__(256) void scan_kernel(
    const float* __restrict__ icH0, const float* __restrict__ ciH0,
    float* __restrict__ out) {

    extern __shared__ float sm[];
    float* Wsm = sm;                 // packed [k4][g][4kk], g in [0,384)
    float* hb  = sm + 49152;         // 16 x 128 (swizzled)
    float* rh  = sm + 49152 + 2048;  // 16 x 128 (swizzled)
    float* Cs  = sm + 49152 + 4096;  // 16 x 256 (swizzled)

    int tid = threadIdx.x;
    int w = tid >> 5;
    int lane = tid & 31;
    int rg = lane >> 3;        // 0..3
    int sub = lane & 7;        // 0..7
    int sw = rg << 3;          // swizzle for this thread's rows (r>>2 == rg)

    int dir = blockIdx.x >> 5;
    int tile = blockIdx.x & 31;
    int b0 = tile * RT;

    const float* h0 = (dir < 2) ? (icH0 + dir * H) : (ciH0 + (dir - 2) * H);

    // load W into SMEM (192 KB), h0 into hb (swizzled)
    {
        const float4* wg = (const float4*)(g_wpk + (size_t)dir * G * H);
        float4* Wsm4 = (float4*)Wsm;
        #pragma unroll
        for (int i = 0; i < (G * H / 4) / 256; i++)
            Wsm4[tid + 256 * i] = wg[tid + 256 * i];
        for (int i = tid; i < RT * H; i += 256) {
            int r = i >> 7, g = i & 127;
            hb[r * 128 + (g ^ (((r >> 2) & 3) << 3))] = h0[g];
        }
    }
    __syncthreads();

    const bool backward = (dir & 1);
    const bool is_ci = (dir >= 2);
    const float* xbase = g_xall + (size_t)b0 * T * NTOT + dir * G;
    const size_t rowstride = (size_t)T * NTOT;

    for (int step = 0; step < T; step++) {
        int t = backward ? (T - 1 - step) : step;
        const float* xt = xbase + (size_t)t * NTOT;

        // prefetch x for gate/update ownership (hidden under GEMM1)
        float xz[4][2], xr[4][2], xn[4][2];
        #pragma unroll
        for (int m = 0; m < 4; m++) {
            const float* xrow = xt + (size_t)(rg * 4 + m) * rowstride;
            #pragma unroll
            for (int l = 0; l < 2; l++) {
                int g = w * 16 + l * 8 + sub;
                xz[m][l] = __ldg(xrow + g);
                xr[m][l] = __ldg(xrow + g + 128);
                xn[m][l] = __ldg(xrow + g + 256);
            }
        }

        // ---- GEMM1: Cs[r][j] = sum_k h[r][k] * W_zr[j][k] ----
        {
            unsigned long long acc[4][4];
            #pragma unroll
            for (int m = 0; m < 4; m++)
                #pragma unroll
                for (int l = 0; l < 4; l++) acc[m][l] = 0ull;
            #pragma unroll 2
            for (int k4 = 0; k4 < H / 4; k4++) {
                ulonglong2 wv[4], hv[4];
                #pragma unroll
                for (int l = 0; l < 4; l++)
                    wv[l] = *(const ulonglong2*)&Wsm[(size_t)(k4 * G + w * 32 + l * 8 + sub) * 4];
                #pragma unroll
                for (int m = 0; m < 4; m++)
                    hv[m] = *(const ulonglong2*)&hb[(rg * 4 + m) * 128 + ((k4 * 4) ^ sw)];
                #pragma unroll
                for (int m = 0; m < 4; m++)
                    #pragma unroll
                    for (int l = 0; l < 4; l++) {
                        ffma2(acc[m][l], hv[m].x, wv[l].x);
                        ffma2(acc[m][l], hv[m].y, wv[l].y);
                    }
            }
            #pragma unroll
            for (int m = 0; m < 4; m++)
                #pragma unroll
                for (int l = 0; l < 4; l++) {
                    int r = rg * 4 + m;
                    int j = w * 32 + l * 8 + sub;
                    Cs[r * 256 + (j ^ sw)] = hsum2(acc[m][l]);
                }
        }
        __syncthreads();

        // ---- gates: z, hb stay in registers; rh = r_gate * h ----
        float z[4][2], hbr[4][2];
        #pragma unroll
        for (int m = 0; m < 4; m++)
            #pragma unroll
            for (int l = 0; l < 2; l++) {
                int r = rg * 4 + m;
                int g = w * 16 + l * 8 + sub;
                float cz = Cs[r * 256 + (g ^ sw)];
                float cr = Cs[r * 256 + ((g + 128) ^ sw)];
                z[m][l] = sigm(xz[m][l] + cz);
                float rgt = sigm(xr[m][l] + cr);
                float hv = hb[r * 128 + (g ^ sw)];
                hbr[m][l] = hv;
                rh[r * 128 + (g ^ sw)] = rgt * hv;
            }
        __syncthreads();

        // ---- GEMM2: n_pre[r][g] = sum_k rh[r][k] * W_n[g][k]; update h ----
        {
            unsigned long long acc[4][2];
            #pragma unroll
            for (int m = 0; m < 4; m++)
                #pragma unroll
                for (int l = 0; l < 2; l++) acc[m][l] = 0ull;
            #pragma unroll 2
            for (int k4 = 0; k4 < H / 4; k4++) {
                ulonglong2 wv[2], hv[4];
                #pragma unroll
                for (int l = 0; l < 2; l++)
                    wv[l] = *(const ulonglong2*)&Wsm[(size_t)(k4 * G + 256 + w * 16 + l * 8 + sub) * 4];
                #pragma unroll
                for (int m = 0; m < 4; m++)
                    hv[m] = *(const ulonglong2*)&rh[(rg * 4 + m) * 128 + ((k4 * 4) ^ sw)];
                #pragma unroll
                for (int m = 0; m < 4; m++)
                    #pragma unroll
                    for (int l = 0; l < 2; l++) {
                        ffma2(acc[m][l], hv[m].x, wv[l].x);
                        ffma2(acc[m][l], hv[m].y, wv[l].y);
                    }
            }
            int slot = is_ci ? (dir == 2 ? t + 1 : t - 1) : 0;
            #pragma unroll
            for (int m = 0; m < 4; m++)
                #pragma unroll
                for (int l = 0; l < 2; l++) {
                    int r = rg * 4 + m;
                    int g = w * 16 + l * 8 + sub;
                    float nv = tanhf(xn[m][l] + hsum2(acc[m][l]));
                    float hn = z[m][l] * hbr[m][l] + (1.0f - z[m][l]) * nv;
                    hn = fminf(CLIPV, fmaxf(-CLIPV, hn));
                    hb[r * 128 + (g ^ sw)] = hn;
                    if (is_ci && slot >= 0 && slot < T) {
                        size_t o = 65536 + (((size_t)(dir - 2) * B + (b0 + r)) * T + slot) * H + g;
                        out[o] = hn;
                    }
                }
        }
        __syncthreads();
    }

    if (dir < 2) {
        for (int i = tid; i < RT * H; i += 256) {
            int r = i >> 7, g = i & 127;
            g_hfinal[((size_t)dir * B + b0 + r) * H + g] =
                hb[r * 128 + (g ^ (((r >> 2) & 3) << 3))];
        }
    }
}

// ---------------- kernel 3: zero the lag-pad slots of ci ----------------
__global__ void zero_pads(float* __restrict__ out) {
    int b = blockIdx.x;
    int g = threadIdx.x;
    out[65536 + ((size_t)b * T + 0) * H + g] = 0.0f;
    out[65536 + (((size_t)B + b) * T + (T - 1)) * H + g] = 0.0f;
}

// ---------------- kernel 4: final linear -> ic_mean, ic_std ----------------
__global__ void final_linear(const float* __restrict__ Wl,
                             const float* __restrict__ bl,
                             float* __restrict__ out) {
    __shared__ float hsm[2 * H];
    int b = blockIdx.x;
    int j = threadIdx.x;
    hsm[j] = g_hfinal[(size_t)b * H + j];
    hsm[H + j] = g_hfinal[((size_t)B + b) * H + j];
    __syncthreads();

    float acc = bl[j];
    const float4* w = (const float4*)&Wl[(size_t)j * (2 * H)];
    #pragma unroll 8
    for (int k4 = 0; k4 < (2 * H) / 4; k4++) {
        float4 wv = w[k4];
        float4 hv = *(const float4*)&hsm[k4 * 4];
        acc += wv.x * hv.x + wv.y * hv.y + wv.z * hv.z + wv.w * hv.w;
    }
    if (j < 64) out[(size_t)b * 64 + j] = acc;
    else out[32768 + (size_t)b * 64 + (j - 64)] = expf(acc);
}

// ---------------- launch ----------------
extern "C" void kernel_launch(void* const* d_in, const int* in_sizes, int n_in,
                              void* d_out, int out_size) {
    const float* data   = (const float*)d_in[0];
    const float* ic_h0  = (const float*)d_in[1];
    const float* ci_h0  = (const float*)d_in[2];
    const float* ic_Wih = (const float*)d_in[3];
    const float* ic_bih = (const float*)d_in[4];
    const float* ic_Whh = (const float*)d_in[5];
    const float* ic_bhh = (const float*)d_in[6];
    const float* ci_Wih = (const float*)d_in[7];
    const float* ci_bih = (const float*)d_in[8];
    const float* ci_Whh = (const float*)d_in[9];
    const float* ci_bhh = (const float*)d_in[10];
    const float* Wl     = (const float*)d_in[11];
    const float* bl     = (const float*)d_in[12];
    float* out = (float*)d_out;

    cudaFuncSetAttribute(scan_kernel, cudaFuncAttributeMaxDynamicSharedMemorySize, SMEM_SCAN);
    cudaFuncSetAttribute(proj_hmma, cudaFuncAttributeMaxDynamicSharedMemorySize, SMEM_PROJ);

    repack_whh<<<(NDIR * G * H + 255) / 256, 256>>>(ic_Whh, ci_Whh);
    conv_data<<<(int)((size_t)B * T * D / 4 / 256), 256>>>(data);
    conv_w<<<NTOT, 256>>>(ic_Wih, ic_bih, ci_Wih, ci_bih, ic_bhh, ci_bhh);

    dim3 pgrid(NTOT / 128, B * T / 128);   // 12 x 2048
    proj_hmma<<<pgrid, 256, SMEM_PROJ>>>();

    scan_kernel<<<NDIR * (B / RT), 256, SMEM_SCAN>>>(ic_h0, ci_h0, out);

    zero_pads<<<B, H>>>(out);
    final_linear<<<B, H>>>(Wl, bl, out);
}